// round 4
// baseline (speedup 1.0000x reference)
#include <cuda_runtime.h>
#include <cstdint>

// Problem constants
#define B_ 4
#define S_ 2048
#define E_ 768
#define H_ 12
#define D_ 64
#define SCALE_ 0.125f   // 1/sqrt(64)

// Scratch (no cudaMalloc allowed)
__device__ float g_q[(size_t)B_ * H_ * S_ * D_];
__device__ float g_k[(size_t)B_ * H_ * S_ * D_];
__device__ float g_v[(size_t)B_ * H_ * S_ * D_];
__device__ float g_x[(size_t)B_ * S_ * E_];      // tf32-rounded X
__device__ float g_w[(size_t)E_ * 3 * E_];       // tf32-rounded W

// ---------------------------------------------------------------------------
// helpers
// ---------------------------------------------------------------------------
__device__ __forceinline__ uint32_t f2t(float f) {
    uint32_t u;
    asm("cvt.rna.tf32.f32 %0, %1;" : "=r"(u) : "f"(f));
    return u;
}

__device__ __forceinline__ void mma8(float c[4],
                                     uint32_t a0, uint32_t a1, uint32_t a2, uint32_t a3,
                                     uint32_t b0, uint32_t b1) {
    asm volatile(
        "mma.sync.aligned.m16n8k8.row.col.f32.tf32.tf32.f32 "
        "{%0,%1,%2,%3}, {%4,%5,%6,%7}, {%8,%9}, {%0,%1,%2,%3};"
        : "+f"(c[0]), "+f"(c[1]), "+f"(c[2]), "+f"(c[3])
        : "r"(a0), "r"(a1), "r"(a2), "r"(a3), "r"(b0), "r"(b1));
}

__device__ __forceinline__ void cp16(void* sdst, const void* gsrc) {
    uint32_t a = (uint32_t)__cvta_generic_to_shared(sdst);
    asm volatile("cp.async.cg.shared.global [%0], [%1], 16;"
                 :: "r"(a), "l"(gsrc));
}
#define CP_COMMIT() asm volatile("cp.async.commit_group;")
#define CP_WAIT0()  asm volatile("cp.async.wait_group 0;")

// ---------------------------------------------------------------------------
// Kernel 0: elementwise rna tf32 rounding
// ---------------------------------------------------------------------------
__global__ void cvt_kernel(const float4* __restrict__ src,
                           uint4* __restrict__ dst, int n4)
{
    int i = blockIdx.x * blockDim.x + threadIdx.x;
    if (i < n4) {
        float4 v = src[i];
        dst[i] = make_uint4(f2t(v.x), f2t(v.y), f2t(v.z), f2t(v.w));
    }
}

// ---------------------------------------------------------------------------
// Kernel 1: fused QKV projection  C[8192,2304] = Xt @ Wt + b  (tf32 mma)
// CTA tile 256x128, 8 warps (4m x 2n), warp tile 64x64 (mi=4, ni=8), BK=32,
// double-buffered cp.async. Epilogue stores Q/K/V rna-rounded into [B,H,S,D].
// ---------------------------------------------------------------------------
#define GA_STRIDE 40
#define GB_STRIDE 140
#define GEMM_SMEM_WORDS (2 * 256 * GA_STRIDE + 2 * 32 * GB_STRIDE)
#define GEMM_SMEM_BYTES (GEMM_SMEM_WORDS * 4)

__global__ __launch_bounds__(256, 1) void qkv_gemm(const float* __restrict__ bias)
{
    extern __shared__ uint32_t shg[];
    uint32_t* As = shg;                         // [2][256][40]
    uint32_t* Bs = shg + 2 * 256 * GA_STRIDE;   // [2][32][140]

    const int tid  = threadIdx.x;
    const int lane = tid & 31;
    const int wid  = tid >> 5;
    const int g    = lane >> 2;
    const int tg   = lane & 3;
    const int wm   = wid & 3;     // 4 warp-rows, 64 rows each
    const int wn   = wid >> 2;    // 2 warp-cols, 64 cols each
    const int mbase = blockIdx.y * 256;
    const int nbase = blockIdx.x * 128;

    const float* X = g_x;
    const float* W = g_w;

    float acc[4][8][4];
#pragma unroll
    for (int mi = 0; mi < 4; mi++)
#pragma unroll
        for (int ni = 0; ni < 8; ni++)
#pragma unroll
            for (int c = 0; c < 4; c++) acc[mi][ni][c] = 0.f;

    auto stage = [&](int buf, int k0) {
        uint32_t* Ab = As + buf * 256 * GA_STRIDE;
        uint32_t* Bb = Bs + buf * 32 * GB_STRIDE;
#pragma unroll
        for (int i = 0; i < 8; i++) {            // A: 256x32
            int j = i * 256 + tid;
            int r = j >> 3, c4 = (j & 7) * 4;
            cp16(&Ab[r * GA_STRIDE + c4],
                 X + (size_t)(mbase + r) * E_ + k0 + c4);
        }
#pragma unroll
        for (int i = 0; i < 4; i++) {            // B: 32x128
            int j = i * 256 + tid;
            int kr = j >> 5, c4 = (j & 31) * 4;
            cp16(&Bb[kr * GB_STRIDE + c4],
                 W + (size_t)(k0 + kr) * (3 * E_) + nbase + c4);
        }
    };

    const int NK = E_ / 32;   // 24
    stage(0, 0);
    CP_COMMIT();

    for (int ks = 0; ks < NK; ks++) {
        CP_WAIT0();
        __syncthreads();
        if (ks + 1 < NK) {
            stage((ks + 1) & 1, (ks + 1) * 32);
            CP_COMMIT();
        }
        uint32_t* Ab = As + (ks & 1) * 256 * GA_STRIDE;
        uint32_t* Bb = Bs + (ks & 1) * 32 * GB_STRIDE;

#pragma unroll
        for (int kk = 0; kk < 4; kk++) {
            uint2 a[4][2];
#pragma unroll
            for (int mi = 0; mi < 4; mi++) {
                int row = wm * 64 + mi * 16 + g;
                a[mi][0] = *reinterpret_cast<const uint2*>(
                    &Ab[row * GA_STRIDE + kk * 8 + 2 * tg]);
                a[mi][1] = *reinterpret_cast<const uint2*>(
                    &Ab[(row + 8) * GA_STRIDE + kk * 8 + 2 * tg]);
            }
#pragma unroll
            for (int ni = 0; ni < 8; ni++) {
                int col = wn * 64 + ni * 8 + g;
                uint32_t b0 = Bb[(kk * 8 + 2 * tg) * GB_STRIDE + col];
                uint32_t b1 = Bb[(kk * 8 + 2 * tg + 1) * GB_STRIDE + col];
#pragma unroll
                for (int mi = 0; mi < 4; mi++)
                    mma8(acc[mi][ni],
                         a[mi][0].x, a[mi][1].x, a[mi][0].y, a[mi][1].y, b0, b1);
            }
        }
    }

    // Epilogue: + bias, rna-round, scatter into g_q/g_k/g_v as [B,H,S,D]
#pragma unroll
    for (int mi = 0; mi < 4; mi++) {
#pragma unroll
        for (int ni = 0; ni < 8; ni++) {
            int n = nbase + wn * 64 + ni * 8 + 2 * tg;   // even
            int which = n / E_;
            int n2 = n - which * E_;
            int h = n2 >> 6, d = n2 & 63;
            float b0 = __ldg(bias + n), b1 = __ldg(bias + n + 1);
            float* basep = (which == 0) ? g_q : ((which == 1) ? g_k : g_v);
#pragma unroll
            for (int half = 0; half < 2; half++) {
                int m = mbase + wm * 64 + mi * 16 + g + half * 8;
                int b = m >> 11;
                int s = m & 2047;
                float2 val = make_float2(
                    __uint_as_float(f2t(acc[mi][ni][half * 2 + 0] + b0)),
                    __uint_as_float(f2t(acc[mi][ni][half * 2 + 1] + b1)));
                *reinterpret_cast<float2*>(
                    basep + ((((size_t)b * H_ + h) * S_ + s) * D_ + d)) = val;
            }
        }
    }
}

// ---------------------------------------------------------------------------
// Kernel 2: causal ReLU attention. q-tile 256, 8 warps x 32 rows (mi=2).
// K/V fragments reused across both row-slabs; register S->P->Y dataflow;
// double-buffered cp.async K/V tiles; heavy q-tiles launched first.
// ---------------------------------------------------------------------------
#define AT_STRIDE 72
#define V_STRIDE  68
#define ATTN_SMEM_WORDS (256 * AT_STRIDE + 2 * 64 * AT_STRIDE + 2 * 64 * V_STRIDE)
#define ATTN_SMEM_BYTES (ATTN_SMEM_WORDS * 4)

__global__ __launch_bounds__(256, 1) void attn_kernel(float* __restrict__ out)
{
    extern __shared__ uint32_t sh[];
    uint32_t* Qs = sh;                               // [256][72]
    uint32_t* Ks = Qs + 256 * AT_STRIDE;             // [2][64][72]
    uint32_t* Vs = Ks + 2 * 64 * AT_STRIDE;          // [2][64][68]

    const int tid  = threadIdx.x;
    const int lane = tid & 31;
    const int w    = tid >> 5;   // warp 0..7, rows [w*32, w*32+32)
    const int g    = lane >> 2;
    const int tg   = lane & 3;
    const int qt   = (gridDim.x - 1) - blockIdx.x;   // heavy tiles first
    const int bh   = blockIdx.y;
    const int qbase = qt * 256;

    const float* Qg = g_q + (size_t)bh * S_ * D_ + (size_t)qbase * D_;
    const float* Kg = g_k + (size_t)bh * S_ * D_;
    const float* Vg = g_v + (size_t)bh * S_ * D_;

    auto stageKV = [&](int buf, int kt) {
        uint32_t* Kb = Ks + buf * 64 * AT_STRIDE;
        uint32_t* Vb = Vs + buf * 64 * V_STRIDE;
        const float* Kt = Kg + (size_t)kt * 64 * 64;
        const float* Vt = Vg + (size_t)kt * 64 * 64;
#pragma unroll
        for (int i = 0; i < 4; i++) {
            int j = i * 256 + tid;
            int r = j >> 4, c4 = (j & 15) * 4;
            cp16(&Kb[r * AT_STRIDE + c4], Kt + r * 64 + c4);
            cp16(&Vb[r * V_STRIDE + c4], Vt + r * 64 + c4);
        }
    };

    // prologue: stage Q (256x64) + first K/V tile
#pragma unroll
    for (int i = 0; i < 16; i++) {
        int j = i * 256 + tid;
        int r = j >> 4, c4 = (j & 15) * 4;
        cp16(&Qs[r * AT_STRIDE + c4], Qg + r * 64 + c4);
    }
    stageKV(0, 0);
    CP_COMMIT();

    float yacc[2][8][4];
#pragma unroll
    for (int mi = 0; mi < 2; mi++)
#pragma unroll
        for (int ni = 0; ni < 8; ni++)
#pragma unroll
            for (int c = 0; c < 4; c++) yacc[mi][ni][c] = 0.f;

    const int nkt = 4 * qt + 4;
    for (int kt = 0; kt < nkt; kt++) {
        CP_WAIT0();
        __syncthreads();
        if (kt + 1 < nkt) {
            stageKV((kt + 1) & 1, kt + 1);
            CP_COMMIT();
        }
        uint32_t* Kb = Ks + (kt & 1) * 64 * AT_STRIDE;
        uint32_t* Vb = Vs + (kt & 1) * 64 * V_STRIDE;

        // ---- S = Q @ K^T : 32 rows x 64 cols, k-depth 64 ----
        float sacc[2][8][4];
#pragma unroll
        for (int mi = 0; mi < 2; mi++)
#pragma unroll
            for (int ni = 0; ni < 8; ni++)
#pragma unroll
                for (int c = 0; c < 4; c++) sacc[mi][ni][c] = 0.f;

#pragma unroll
        for (int kk = 0; kk < 8; kk++) {
            uint2 a[2][2];
#pragma unroll
            for (int mi = 0; mi < 2; mi++) {
                int row = w * 32 + mi * 16 + g;
                a[mi][0] = *reinterpret_cast<const uint2*>(
                    &Qs[row * AT_STRIDE + kk * 8 + 2 * tg]);
                a[mi][1] = *reinterpret_cast<const uint2*>(
                    &Qs[(row + 8) * AT_STRIDE + kk * 8 + 2 * tg]);
            }
#pragma unroll
            for (int ni = 0; ni < 8; ni++) {
                uint2 b = *reinterpret_cast<const uint2*>(
                    &Kb[(ni * 8 + g) * AT_STRIDE + kk * 8 + 2 * tg]);
#pragma unroll
                for (int mi = 0; mi < 2; mi++)
                    mma8(sacc[mi][ni], a[mi][0].x, a[mi][1].x,
                         a[mi][0].y, a[mi][1].y, b.x, b.y);
            }
        }

        // ---- scale, causal mask, relu, cvt->tf32 IN PLACE ----
        const bool need_mask = (kt >= 4 * qt);
#pragma unroll
        for (int mi = 0; mi < 2; mi++) {
            const int r0 = qbase + w * 32 + mi * 16 + g;
#pragma unroll
            for (int ni = 0; ni < 8; ni++) {
                int c0 = kt * 64 + ni * 8 + 2 * tg;
                float v0 = fmaxf(sacc[mi][ni][0] * SCALE_, 0.f);
                float v1 = fmaxf(sacc[mi][ni][1] * SCALE_, 0.f);
                float v2 = fmaxf(sacc[mi][ni][2] * SCALE_, 0.f);
                float v3 = fmaxf(sacc[mi][ni][3] * SCALE_, 0.f);
                if (need_mask) {
                    if (c0 > r0)         v0 = 0.f;
                    if (c0 + 1 > r0)     v1 = 0.f;
                    if (c0 > r0 + 8)     v2 = 0.f;
                    if (c0 + 1 > r0 + 8) v3 = 0.f;
                }
                sacc[mi][ni][0] = __uint_as_float(f2t(v0));
                sacc[mi][ni][1] = __uint_as_float(f2t(v1));
                sacc[mi][ni][2] = __uint_as_float(f2t(v2));
                sacc[mi][ni][3] = __uint_as_float(f2t(v3));
            }
        }

        // ---- Y += P @ V : P lives in sacc (C frag == A frag), V shared ----
#pragma unroll
        for (int kk = 0; kk < 8; kk++) {
#pragma unroll
            for (int ni = 0; ni < 8; ni++) {
                uint32_t b0 = Vb[(kk * 8 + 2 * tg) * V_STRIDE + ni * 8 + g];
                uint32_t b1 = Vb[(kk * 8 + 2 * tg + 1) * V_STRIDE + ni * 8 + g];
#pragma unroll
                for (int mi = 0; mi < 2; mi++)
                    mma8(yacc[mi][ni],
                         __float_as_uint(sacc[mi][kk][0]),
                         __float_as_uint(sacc[mi][kk][2]),
                         __float_as_uint(sacc[mi][kk][1]),
                         __float_as_uint(sacc[mi][kk][3]),
                         b0, b1);
            }
        }
    }

    // ---- write Y to out [B, S, H, D] ----
    const int b = bh / H_, h = bh % H_;
#pragma unroll
    for (int mi = 0; mi < 2; mi++) {
        const int r0 = qbase + w * 32 + mi * 16 + g;
#pragma unroll
        for (int ni = 0; ni < 8; ni++) {
            int d0 = ni * 8 + 2 * tg;
            float2 v0 = make_float2(yacc[mi][ni][0], yacc[mi][ni][1]);
            *reinterpret_cast<float2*>(
                &out[(((size_t)b * S_ + r0) * H_ + h) * D_ + d0]) = v0;
            float2 v1 = make_float2(yacc[mi][ni][2], yacc[mi][ni][3]);
            *reinterpret_cast<float2*>(
                &out[(((size_t)b * S_ + r0 + 8) * H_ + h) * D_ + d0]) = v1;
        }
    }
}

// ---------------------------------------------------------------------------
extern "C" void kernel_launch(void* const* d_in, const int* in_sizes, int n_in,
                              void* d_out, int out_size)
{
    const float* X    = (const float*)d_in[0];   // [4, 2048, 768]
    const float* W    = (const float*)d_in[1];   // [768, 2304]
    const float* bias = (const float*)d_in[2];   // [2304]
    float* out = (float*)d_out;                  // [4, 2048, 768]

    static bool attr_done = false;
    if (!attr_done) {
        cudaFuncSetAttribute(qkv_gemm,
                             cudaFuncAttributeMaxDynamicSharedMemorySize,
                             GEMM_SMEM_BYTES);
        cudaFuncSetAttribute(attn_kernel,
                             cudaFuncAttributeMaxDynamicSharedMemorySize,
                             ATTN_SMEM_BYTES);
        attr_done = true;
    }

    // round inputs to tf32 once per launch (deterministic, idempotent)
    {
        float* gx;  cudaGetSymbolAddress((void**)&gx, g_x);
        float* gw;  cudaGetSymbolAddress((void**)&gw, g_w);
        int nx4 = (B_ * S_ * E_) / 4;
        int nw4 = (E_ * 3 * E_) / 4;
        cvt_kernel<<<(nx4 + 255) / 256, 256>>>(
            (const float4*)X, (uint4*)gx, nx4);
        cvt_kernel<<<(nw4 + 255) / 256, 256>>>(
            (const float4*)W, (uint4*)gw, nw4);
    }

    qkv_gemm<<<dim3(3 * E_ / 128, (B_ * S_) / 256), 256, GEMM_SMEM_BYTES>>>(bias);
    attn_kernel<<<dim3(S_ / 256, B_ * H_), 256, ATTN_SMEM_BYTES>>>(out);
}

// round 6
// speedup vs baseline: 1.0432x; 1.0432x over previous
#include <cuda_runtime.h>
#include <cstdint>

// Problem constants
#define B_ 4
#define S_ 2048
#define E_ 768
#define H_ 12
#define D_ 64
#define SCALE_ 0.125f   // 1/sqrt(64)

// Scratch (no cudaMalloc allowed)
__device__ float g_q[(size_t)B_ * H_ * S_ * D_];
__device__ float g_k[(size_t)B_ * H_ * S_ * D_];
__device__ float g_v[(size_t)B_ * H_ * S_ * D_];
__device__ float g_x[(size_t)B_ * S_ * E_];      // tf32-rounded X
__device__ float g_w[(size_t)E_ * 3 * E_];       // tf32-rounded W

// ---------------------------------------------------------------------------
// helpers
// ---------------------------------------------------------------------------
__device__ __forceinline__ uint32_t f2t(float f) {
    uint32_t u;
    asm("cvt.rna.tf32.f32 %0, %1;" : "=r"(u) : "f"(f));
    return u;
}

__device__ __forceinline__ void mma8(float c[4],
                                     uint32_t a0, uint32_t a1, uint32_t a2, uint32_t a3,
                                     uint32_t b0, uint32_t b1) {
    asm volatile(
        "mma.sync.aligned.m16n8k8.row.col.f32.tf32.tf32.f32 "
        "{%0,%1,%2,%3}, {%4,%5,%6,%7}, {%8,%9}, {%0,%1,%2,%3};"
        : "+f"(c[0]), "+f"(c[1]), "+f"(c[2]), "+f"(c[3])
        : "r"(a0), "r"(a1), "r"(a2), "r"(a3), "r"(b0), "r"(b1));
}

__device__ __forceinline__ void cp16(void* sdst, const void* gsrc) {
    uint32_t a = (uint32_t)__cvta_generic_to_shared(sdst);
    asm volatile("cp.async.cg.shared.global [%0], [%1], 16;"
                 :: "r"(a), "l"(gsrc));
}
#define CP_COMMIT() asm volatile("cp.async.commit_group;")
#define CP_WAIT0()  asm volatile("cp.async.wait_group 0;")

// ---------------------------------------------------------------------------
// Kernel 0: elementwise rna tf32 rounding
// ---------------------------------------------------------------------------
__global__ void cvt_kernel(const float4* __restrict__ src,
                           uint4* __restrict__ dst, int n4)
{
    int i = blockIdx.x * blockDim.x + threadIdx.x;
    if (i < n4) {
        float4 v = src[i];
        dst[i] = make_uint4(f2t(v.x), f2t(v.y), f2t(v.z), f2t(v.w));
    }
}

// ---------------------------------------------------------------------------
// Kernel 1: fused QKV projection  C[8192,2304] = Xt @ Wt + b  (tf32 mma)
// CTA tile 256x128, 512 threads = 16 warps (8m x 2n), warp tile 32x64
// (mi=2, ni=8), BK=32, double-buffered cp.async. Epilogue stores Q/K/V
// rna-rounded into [B,H,S,D] scratch.
// ---------------------------------------------------------------------------
#define GA_STRIDE 40
#define GB_STRIDE 140
#define GEMM_SMEM_WORDS (2 * 256 * GA_STRIDE + 2 * 32 * GB_STRIDE)
#define GEMM_SMEM_BYTES (GEMM_SMEM_WORDS * 4)

__global__ __launch_bounds__(512, 1) void qkv_gemm(const float* __restrict__ bias)
{
    extern __shared__ uint32_t shg[];
    uint32_t* As = shg;                         // [2][256][40]
    uint32_t* Bs = shg + 2 * 256 * GA_STRIDE;   // [2][32][140]

    const int tid  = threadIdx.x;
    const int lane = tid & 31;
    const int wid  = tid >> 5;
    const int g    = lane >> 2;
    const int tg   = lane & 3;
    const int wm   = wid & 7;     // 8 warp-rows, 32 rows each
    const int wn   = wid >> 3;    // 2 warp-cols, 64 cols each
    const int mbase = blockIdx.y * 256;
    const int nbase = blockIdx.x * 128;

    const float* X = g_x;
    const float* W = g_w;

    float acc[2][8][4];
#pragma unroll
    for (int mi = 0; mi < 2; mi++)
#pragma unroll
        for (int ni = 0; ni < 8; ni++)
#pragma unroll
            for (int c = 0; c < 4; c++) acc[mi][ni][c] = 0.f;

    auto stage = [&](int buf, int k0) {
        uint32_t* Ab = As + buf * 256 * GA_STRIDE;
        uint32_t* Bb = Bs + buf * 32 * GB_STRIDE;
#pragma unroll
        for (int i = 0; i < 4; i++) {            // A: 256x32 = 2048 chunks
            int j = i * 512 + tid;
            int r = j >> 3, c4 = (j & 7) * 4;
            cp16(&Ab[r * GA_STRIDE + c4],
                 X + (size_t)(mbase + r) * E_ + k0 + c4);
        }
#pragma unroll
        for (int i = 0; i < 2; i++) {            // B: 32x128 = 1024 chunks
            int j = i * 512 + tid;
            int kr = j >> 5, c4 = (j & 31) * 4;
            cp16(&Bb[kr * GB_STRIDE + c4],
                 W + (size_t)(k0 + kr) * (3 * E_) + nbase + c4);
        }
    };

    const int NK = E_ / 32;   // 24
    stage(0, 0);
    CP_COMMIT();

    for (int ks = 0; ks < NK; ks++) {
        CP_WAIT0();
        __syncthreads();
        if (ks + 1 < NK) {
            stage((ks + 1) & 1, (ks + 1) * 32);
            CP_COMMIT();
        }
        uint32_t* Ab = As + (ks & 1) * 256 * GA_STRIDE;
        uint32_t* Bb = Bs + (ks & 1) * 32 * GB_STRIDE;

#pragma unroll
        for (int kk = 0; kk < 4; kk++) {
            uint2 a[2][2];
#pragma unroll
            for (int mi = 0; mi < 2; mi++) {
                int row = wm * 32 + mi * 16 + g;
                a[mi][0] = *reinterpret_cast<const uint2*>(
                    &Ab[row * GA_STRIDE + kk * 8 + 2 * tg]);
                a[mi][1] = *reinterpret_cast<const uint2*>(
                    &Ab[(row + 8) * GA_STRIDE + kk * 8 + 2 * tg]);
            }
#pragma unroll
            for (int ni = 0; ni < 8; ni++) {
                int col = wn * 64 + ni * 8 + g;
                uint32_t b0 = Bb[(kk * 8 + 2 * tg) * GB_STRIDE + col];
                uint32_t b1 = Bb[(kk * 8 + 2 * tg + 1) * GB_STRIDE + col];
#pragma unroll
                for (int mi = 0; mi < 2; mi++)
                    mma8(acc[mi][ni],
                         a[mi][0].x, a[mi][1].x, a[mi][0].y, a[mi][1].y, b0, b1);
            }
        }
    }

    // Epilogue: + bias, rna-round, scatter into g_q/g_k/g_v as [B,H,S,D]
#pragma unroll
    for (int mi = 0; mi < 2; mi++) {
#pragma unroll
        for (int ni = 0; ni < 8; ni++) {
            int n = nbase + wn * 64 + ni * 8 + 2 * tg;   // even
            int which = n / E_;
            int n2 = n - which * E_;
            int h = n2 >> 6, d = n2 & 63;
            float b0 = __ldg(bias + n), b1 = __ldg(bias + n + 1);
            float* basep = (which == 0) ? g_q : ((which == 1) ? g_k : g_v);
#pragma unroll
            for (int half = 0; half < 2; half++) {
                int m = mbase + wm * 32 + mi * 16 + g + half * 8;
                int b = m >> 11;
                int s = m & 2047;
                float2 val = make_float2(
                    __uint_as_float(f2t(acc[mi][ni][half * 2 + 0] + b0)),
                    __uint_as_float(f2t(acc[mi][ni][half * 2 + 1] + b1)));
                *reinterpret_cast<float2*>(
                    basep + ((((size_t)b * H_ + h) * S_ + s) * D_ + d)) = val;
            }
        }
    }
}

// ---------------------------------------------------------------------------
// Kernel 2: causal ReLU attention. 8 warps x 16 q-rows, register S->P->Y
// dataflow, double-buffered cp.async K/V tiles, heavy q-tiles first,
// diagonal-tile MMA skipping (nlim).
// ---------------------------------------------------------------------------
#define AT_STRIDE 72
#define V_STRIDE  68
#define ATTN_SMEM_WORDS (128 * AT_STRIDE + 2 * 64 * AT_STRIDE + 2 * 64 * V_STRIDE)
#define ATTN_SMEM_BYTES (ATTN_SMEM_WORDS * 4)

__global__ __launch_bounds__(256, 2) void attn_kernel(float* __restrict__ out)
{
    extern __shared__ uint32_t sh[];
    uint32_t* Qs = sh;                               // [128][72]
    uint32_t* Ks = Qs + 128 * AT_STRIDE;             // [2][64][72]
    uint32_t* Vs = Ks + 2 * 64 * AT_STRIDE;          // [2][64][68]

    const int tid  = threadIdx.x;
    const int lane = tid & 31;
    const int w    = tid >> 5;
    const int g    = lane >> 2;
    const int tg   = lane & 3;
    const int qt   = (gridDim.x - 1) - blockIdx.x;   // heavy tiles first
    const int bh   = blockIdx.y;
    const int qbase = qt * 128;

    const float* Qg = g_q + (size_t)bh * S_ * D_ + (size_t)qbase * D_;
    const float* Kg = g_k + (size_t)bh * S_ * D_;
    const float* Vg = g_v + (size_t)bh * S_ * D_;

    auto stageKV = [&](int buf, int kt) {
        uint32_t* Kb = Ks + buf * 64 * AT_STRIDE;
        uint32_t* Vb = Vs + buf * 64 * V_STRIDE;
        const float* Kt = Kg + (size_t)kt * 64 * 64;
        const float* Vt = Vg + (size_t)kt * 64 * 64;
#pragma unroll
        for (int i = 0; i < 4; i++) {
            int j = i * 256 + tid;
            int r = j >> 4, c4 = (j & 15) * 4;
            cp16(&Kb[r * AT_STRIDE + c4], Kt + r * 64 + c4);
            cp16(&Vb[r * V_STRIDE + c4], Vt + r * 64 + c4);
        }
    };

#pragma unroll
    for (int i = 0; i < 8; i++) {
        int j = i * 256 + tid;
        int r = j >> 4, c4 = (j & 15) * 4;
        cp16(&Qs[r * AT_STRIDE + c4], Qg + r * 64 + c4);
    }
    stageKV(0, 0);
    CP_COMMIT();

    float yacc[8][4];
#pragma unroll
    for (int ni = 0; ni < 8; ni++)
#pragma unroll
        for (int c = 0; c < 4; c++) yacc[ni][c] = 0.f;

    const int r0 = qbase + w * 16 + g;
    const int qrow0 = w * 16 + g;

    const int nkt = 2 * qt + 2;
    for (int kt = 0; kt < nkt; kt++) {
        CP_WAIT0();
        __syncthreads();
        if (kt + 1 < nkt) {
            stageKV((kt + 1) & 1, kt + 1);
            CP_COMMIT();
        }
        uint32_t* Kb = Ks + (kt & 1) * 64 * AT_STRIDE;
        uint32_t* Vb = Vs + (kt & 1) * 64 * V_STRIDE;

        // active ni/kk groups for this warp in this tile (causal skipping)
        const int tile_d = kt - 2 * qt;
        int nlim = 8;
        if (tile_d >= 0) {
            nlim = 2 * w + 2 - 8 * tile_d;
            if (nlim > 8) nlim = 8;
            if (nlim < 0) nlim = 0;
        }
        if (nlim == 0) continue;   // fully masked for this warp: skip compute

        // ---- S = Q @ K^T : 16 rows x (nlim*8) cols, k-depth 64 ----
        float sacc[8][4];
#pragma unroll
        for (int ni = 0; ni < 8; ni++)
#pragma unroll
            for (int c = 0; c < 4; c++) sacc[ni][c] = 0.f;

#pragma unroll
        for (int kk = 0; kk < 8; kk++) {
            uint2 a0 = *reinterpret_cast<const uint2*>(
                &Qs[qrow0 * AT_STRIDE + kk * 8 + 2 * tg]);
            uint2 a1 = *reinterpret_cast<const uint2*>(
                &Qs[(qrow0 + 8) * AT_STRIDE + kk * 8 + 2 * tg]);
#pragma unroll
            for (int ni = 0; ni < 8; ni++) {
                if (ni < nlim) {
                    uint2 b = *reinterpret_cast<const uint2*>(
                        &Kb[(ni * 8 + g) * AT_STRIDE + kk * 8 + 2 * tg]);
                    mma8(sacc[ni], a0.x, a1.x, a0.y, a1.y, b.x, b.y);
                }
            }
        }

        // ---- scale, causal mask, relu, cvt->tf32 IN PLACE ----
        const bool need_mask = (tile_d >= 0);
#pragma unroll
        for (int ni = 0; ni < 8; ni++) {
            if (ni < nlim) {
                int c0 = kt * 64 + ni * 8 + 2 * tg;
                float v0 = fmaxf(sacc[ni][0] * SCALE_, 0.f);
                float v1 = fmaxf(sacc[ni][1] * SCALE_, 0.f);
                float v2 = fmaxf(sacc[ni][2] * SCALE_, 0.f);
                float v3 = fmaxf(sacc[ni][3] * SCALE_, 0.f);
                if (need_mask) {
                    if (c0 > r0)         v0 = 0.f;
                    if (c0 + 1 > r0)     v1 = 0.f;
                    if (c0 > r0 + 8)     v2 = 0.f;
                    if (c0 + 1 > r0 + 8) v3 = 0.f;
                }
                sacc[ni][0] = __uint_as_float(f2t(v0));
                sacc[ni][1] = __uint_as_float(f2t(v1));
                sacc[ni][2] = __uint_as_float(f2t(v2));
                sacc[ni][3] = __uint_as_float(f2t(v3));
            }
        }

        // ---- Y += P @ V : P in registers (C frag == A frag) ----
#pragma unroll
        for (int kk = 0; kk < 8; kk++) {
            if (kk < nlim) {
                uint32_t a0 = __float_as_uint(sacc[kk][0]);
                uint32_t a1 = __float_as_uint(sacc[kk][2]);
                uint32_t a2 = __float_as_uint(sacc[kk][1]);
                uint32_t a3 = __float_as_uint(sacc[kk][3]);
#pragma unroll
                for (int ni = 0; ni < 8; ni++) {
                    uint32_t b0 = Vb[(kk * 8 + 2 * tg) * V_STRIDE + ni * 8 + g];
                    uint32_t b1 = Vb[(kk * 8 + 2 * tg + 1) * V_STRIDE + ni * 8 + g];
                    mma8(yacc[ni], a0, a1, a2, a3, b0, b1);
                }
            }
        }
    }

    // ---- write Y to out [B, S, H, D] ----
    const int b = bh / H_, h = bh % H_;
#pragma unroll
    for (int ni = 0; ni < 8; ni++) {
        int d0 = ni * 8 + 2 * tg;
        float2 v0 = make_float2(yacc[ni][0], yacc[ni][1]);
        *reinterpret_cast<float2*>(
            &out[(((size_t)b * S_ + r0) * H_ + h) * D_ + d0]) = v0;
        float2 v1 = make_float2(yacc[ni][2], yacc[ni][3]);
        *reinterpret_cast<float2*>(
            &out[(((size_t)b * S_ + r0 + 8) * H_ + h) * D_ + d0]) = v1;
    }
}

// ---------------------------------------------------------------------------
extern "C" void kernel_launch(void* const* d_in, const int* in_sizes, int n_in,
                              void* d_out, int out_size)
{
    const float* X    = (const float*)d_in[0];   // [4, 2048, 768]
    const float* W    = (const float*)d_in[1];   // [768, 2304]
    const float* bias = (const float*)d_in[2];   // [2304]
    float* out = (float*)d_out;                  // [4, 2048, 768]

    static bool attr_done = false;
    if (!attr_done) {
        cudaFuncSetAttribute(qkv_gemm,
                             cudaFuncAttributeMaxDynamicSharedMemorySize,
                             GEMM_SMEM_BYTES);
        cudaFuncSetAttribute(attn_kernel,
                             cudaFuncAttributeMaxDynamicSharedMemorySize,
                             ATTN_SMEM_BYTES);
        attr_done = true;
    }

    // round inputs to tf32 once per launch (deterministic, idempotent)
    {
        float* gx;  cudaGetSymbolAddress((void**)&gx, g_x);
        float* gw;  cudaGetSymbolAddress((void**)&gw, g_w);
        int nx4 = (B_ * S_ * E_) / 4;
        int nw4 = (E_ * 3 * E_) / 4;
        cvt_kernel<<<(nx4 + 255) / 256, 256>>>(
            (const float4*)X, (uint4*)gx, nx4);
        cvt_kernel<<<(nw4 + 255) / 256, 256>>>(
            (const float4*)W, (uint4*)gw, nw4);
    }

    qkv_gemm<<<dim3(3 * E_ / 128, (B_ * S_) / 256), 512, GEMM_SMEM_BYTES>>>(bias);
    attn_kernel<<<dim3(S_ / 128, B_ * H_), 256, ATTN_SMEM_BYTES>>>(out);
}

// round 7
// speedup vs baseline: 1.9138x; 1.8345x over previous
#include <cuda_runtime.h>
#include <cuda_fp16.h>
#include <cstdint>

// Problem constants
#define B_ 4
#define S_ 2048
#define E_ 768
#define H_ 12
#define D_ 64
#define SCALE_ 0.125f   // 1/sqrt(64)

// Scratch (no cudaMalloc allowed). All fp16 operand tensors use a
// pair-permuted k-layout: within each 16-element k-group, pair p (elements
// 2p,2p+1) is stored at slot s = 2*(p&3)+(p>>2)  (slots 2t <- pair t,
// slots 2t+1 <- pair t+4), so every mma fragment load is one LDS.64.
__device__ __align__(16) __half g_x[(size_t)B_ * S_ * E_];       // [m][k-perm]
__device__ __align__(16) __half g_w[(size_t)3 * E_ * E_];        // W^T [n][k-perm]
__device__ __align__(16) __half g_q[(size_t)B_ * H_ * S_ * D_];  // [bh][s][d-perm]
__device__ __align__(16) __half g_k[(size_t)B_ * H_ * S_ * D_];  // [bh][s][d-perm]
__device__ __align__(16) __half g_vtmp[(size_t)B_ * H_ * S_ * D_]; // [bh][s][d] natural
__device__ __align__(16) __half g_vt[(size_t)B_ * H_ * S_ * D_];   // [bh][d][s-perm]

// ---------------------------------------------------------------------------
// helpers
// ---------------------------------------------------------------------------
__device__ __forceinline__ int perm16(int j) {     // j in 0..15 -> permuted pos
    int p = j >> 1;                                // pair 0..7
    int slot = 2 * (p & 3) + (p >> 2);
    return 2 * slot + (j & 1);
}

__device__ __forceinline__ uint32_t packh2(float lo, float hi) {
    __half2 h = __floats2half2_rn(lo, hi);         // x = lo, y = hi
    return *reinterpret_cast<uint32_t*>(&h);
}

__device__ __forceinline__ void mma16(float c[4],
                                      uint32_t a0, uint32_t a1, uint32_t a2, uint32_t a3,
                                      uint32_t b0, uint32_t b1) {
    asm volatile(
        "mma.sync.aligned.m16n8k16.row.col.f32.f16.f16.f32 "
        "{%0,%1,%2,%3}, {%4,%5,%6,%7}, {%8,%9}, {%0,%1,%2,%3};"
        : "+f"(c[0]), "+f"(c[1]), "+f"(c[2]), "+f"(c[3])
        : "r"(a0), "r"(a1), "r"(a2), "r"(a3), "r"(b0), "r"(b1));
}

__device__ __forceinline__ void cp16(void* sdst, const void* gsrc) {
    uint32_t a = (uint32_t)__cvta_generic_to_shared(sdst);
    asm volatile("cp.async.cg.shared.global [%0], [%1], 16;"
                 :: "r"(a), "l"(gsrc));
}
#define CP_COMMIT() asm volatile("cp.async.commit_group;")
#define CP_WAIT0()  asm volatile("cp.async.wait_group 0;")

// ---------------------------------------------------------------------------
// Prep A: X [8192][768] f32 -> g_x fp16 with per-16-group pair permutation
// ---------------------------------------------------------------------------
__global__ void cvtx(const float* __restrict__ X, int ngroups)
{
    int i = blockIdx.x * blockDim.x + threadIdx.x;
    if (i >= ngroups) return;
    const float* src = X + (size_t)i * 16;
    __half o[16];
#pragma unroll
    for (int j = 0; j < 16; j++)
        o[perm16(j)] = __float2half_rn(src[j]);
    uint4* dst = reinterpret_cast<uint4*>(g_x + (size_t)i * 16);
    dst[0] = *reinterpret_cast<uint4*>(&o[0]);
    dst[1] = *reinterpret_cast<uint4*>(&o[8]);
}

// ---------------------------------------------------------------------------
// Prep B: W [768][2304] f32 -> g_w = W^T fp16 [2304][768], k pair-permuted
// ---------------------------------------------------------------------------
__global__ void cvtw(const float* __restrict__ W)
{
    __shared__ float t[32][33];
    int n0 = blockIdx.x * 32, k0 = blockIdx.y * 32;
    for (int i = threadIdx.y; i < 32; i += 8)
        t[i][threadIdx.x] = W[(size_t)(k0 + i) * (3 * E_) + n0 + threadIdx.x];
    __syncthreads();
    int kperm = k0 + ((threadIdx.x & ~15) | perm16(threadIdx.x & 15));
    for (int r = threadIdx.y; r < 32; r += 8) {
        float v = t[threadIdx.x][r];   // = W[k0+tx][n0+r]
        g_w[(size_t)(n0 + r) * E_ + kperm] = __float2half_rn(v);
    }
}

// ---------------------------------------------------------------------------
// Prep C (after GEMM): g_vtmp [bh][s][d] -> g_vt [bh][d][s-perm]
// ---------------------------------------------------------------------------
__global__ void vtrans()
{
    __shared__ __half t[64][65];
    int sb = blockIdx.x * 64, bh = blockIdx.y;
    int tid = threadIdx.x;
    const uint32_t* src = reinterpret_cast<const uint32_t*>(
        g_vtmp + ((size_t)bh * S_ + sb) * D_);
#pragma unroll
    for (int i = 0; i < 8; i++) {
        int j = i * 256 + tid;
        int r = j >> 5, c2 = j & 31;
        uint32_t wv = src[r * 32 + c2];
        __half2 h = *reinterpret_cast<__half2*>(&wv);
        t[r][2 * c2]     = __low2half(h);
        t[r][2 * c2 + 1] = __high2half(h);
    }
    __syncthreads();
#pragma unroll
    for (int i = 0; i < 8; i++) {
        int j = i * 256 + tid;
        int d = j >> 5, sl = j & 31;
        int grp = sl >> 3, ws = sl & 7;
        int p = (ws & 1) ? (ws >> 1) + 4 : (ws >> 1);   // slot -> pair
        int s0 = grp * 16 + 2 * p;
        __half2 h2 = __halves2half2(t[s0][d], t[s0 + 1][d]);
        reinterpret_cast<uint32_t*>(
            g_vt + ((size_t)bh * D_ + d) * S_ + sb)[sl] =
            *reinterpret_cast<uint32_t*>(&h2);
    }
}

// ---------------------------------------------------------------------------
// Kernel 1: QKV projection, fp16 m16n8k16 mma.
// CTA 128x128, 8 warps (4m x 2n), warp 32x64, BK=64, double-buffered cp.async.
// Epilogue: +bias, round to fp16, scatter Q/K (d-perm) and V (natural).
// ---------------------------------------------------------------------------
#define GST 40   // smem row stride in 4B words (32 data + 8 pad)
#define GEMM_TILE_W (128 * GST)             // words per tile buffer
#define GEMM_SMEM_BYTES (4 * GEMM_TILE_W * 4)   // A[2] + B[2]

__global__ __launch_bounds__(256, 2) void qkv_gemm(const float* __restrict__ bias)
{
    extern __shared__ uint32_t shg[];
    uint32_t* As = shg;                      // [2][128][40]
    uint32_t* Bs = shg + 2 * GEMM_TILE_W;    // [2][128][40]

    const int tid  = threadIdx.x;
    const int lane = tid & 31;
    const int wid  = tid >> 5;
    const int g    = lane >> 2;
    const int tg   = lane & 3;
    const int wm   = wid & 3;     // 4 warp-rows, 32 rows each
    const int wn   = wid >> 2;    // 2 warp-cols, 64 cols each
    const int mbase = blockIdx.y * 128;
    const int nbase = blockIdx.x * 128;

    float acc[2][8][4];
#pragma unroll
    for (int mi = 0; mi < 2; mi++)
#pragma unroll
        for (int ni = 0; ni < 8; ni++)
#pragma unroll
            for (int c = 0; c < 4; c++) acc[mi][ni][c] = 0.f;

    auto stage = [&](int buf, int k0) {      // k0 in halves, multiple of 64
        uint32_t* Ab = As + buf * GEMM_TILE_W;
        uint32_t* Bb = Bs + buf * GEMM_TILE_W;
#pragma unroll
        for (int i = 0; i < 4; i++) {        // 1024 chunks each for A and B
            int j = i * 256 + tid;
            int r = j >> 3, c = j & 7;
            cp16(&Ab[r * GST + c * 4], g_x + (size_t)(mbase + r) * E_ + k0 + c * 8);
            cp16(&Bb[r * GST + c * 4], g_w + (size_t)(nbase + r) * E_ + k0 + c * 8);
        }
    };

    const int NK = E_ / 64;   // 12
    stage(0, 0);
    CP_COMMIT();

    for (int ks = 0; ks < NK; ks++) {
        CP_WAIT0();
        __syncthreads();
        if (ks + 1 < NK) {
            stage((ks + 1) & 1, (ks + 1) * 64);
            CP_COMMIT();
        }
        uint32_t* Ab = As + (ks & 1) * GEMM_TILE_W;
        uint32_t* Bb = Bs + (ks & 1) * GEMM_TILE_W;

#pragma unroll
        for (int kk = 0; kk < 4; kk++) {
            uint2 a[2][2];
#pragma unroll
            for (int mi = 0; mi < 2; mi++) {
                int row = wm * 32 + mi * 16 + g;
                a[mi][0] = *reinterpret_cast<const uint2*>(   // {a0, a2}
                    &Ab[row * GST + kk * 8 + 2 * tg]);
                a[mi][1] = *reinterpret_cast<const uint2*>(   // {a1, a3}
                    &Ab[(row + 8) * GST + kk * 8 + 2 * tg]);
            }
#pragma unroll
            for (int ni = 0; ni < 8; ni++) {
                uint2 b = *reinterpret_cast<const uint2*>(    // {b0, b1}
                    &Bb[(wn * 64 + ni * 8 + g) * GST + kk * 8 + 2 * tg]);
#pragma unroll
                for (int mi = 0; mi < 2; mi++)
                    mma16(acc[mi][ni],
                          a[mi][0].x, a[mi][1].x, a[mi][0].y, a[mi][1].y,
                          b.x, b.y);
            }
        }
    }

    // Epilogue: +bias, fp16-round, scatter
#pragma unroll
    for (int mi = 0; mi < 2; mi++) {
#pragma unroll
        for (int ni = 0; ni < 8; ni++) {
            int n = nbase + wn * 64 + ni * 8 + 2 * tg;   // even
            int which = n / E_;
            int n2 = n - which * E_;
            int h = n2 >> 6, d = n2 & 63;
            float b0 = __ldg(bias + n), b1 = __ldg(bias + n + 1);
#pragma unroll
            for (int half = 0; half < 2; half++) {
                int m = mbase + wm * 32 + mi * 16 + g + half * 8;
                int bb = m >> 11;
                int ss = m & 2047;
                uint32_t pw = packh2(acc[mi][ni][half * 2 + 0] + b0,
                                     acc[mi][ni][half * 2 + 1] + b1);
                size_t rowbase = (((size_t)bb * H_ + h) * S_ + ss);
                if (which == 2) {
                    *reinterpret_cast<uint32_t*>(g_vtmp + rowbase * D_ + d) = pw;
                } else {
                    int p = (d & 15) >> 1;
                    int slot = 2 * (p & 3) + (p >> 2);
                    int word = (d >> 4) * 8 + slot;
                    __half* basep = which ? g_k : g_q;
                    reinterpret_cast<uint32_t*>(basep + rowbase * D_)[word] = pw;
                }
            }
        }
    }
}

// ---------------------------------------------------------------------------
// Kernel 2: causal ReLU attention, fp16 m16n8k16 mma.
// 8 warps x 16 q-rows, Q frags hoisted to registers, register S->P->Y
// dataflow (S C-frags pack into Y A-frags), double-buffered cp.async K/V.
// ---------------------------------------------------------------------------
#define AST 40   // smem row stride in words
#define ATTN_SMEM_WORDS (128 * AST + 2 * 64 * AST + 2 * 64 * AST)
#define ATTN_SMEM_BYTES (ATTN_SMEM_WORDS * 4)

__global__ __launch_bounds__(256, 2) void attn_kernel(float* __restrict__ out)
{
    extern __shared__ uint32_t sh[];
    uint32_t* Qs = sh;                       // [128][40]
    uint32_t* Ks = Qs + 128 * AST;           // [2][64][40]  K tile [s][d-slots]
    uint32_t* Vs = Ks + 2 * 64 * AST;        // [2][64][40]  V tile [d][s-slots]

    const int tid  = threadIdx.x;
    const int lane = tid & 31;
    const int w    = tid >> 5;
    const int g    = lane >> 2;
    const int tg   = lane & 3;
    const int qt   = blockIdx.x;
    const int bh   = blockIdx.y;
    const int qbase = qt * 128;

    const __half* Qg = g_q + ((size_t)bh * S_ + qbase) * D_;
    const __half* Kg = g_k + (size_t)bh * S_ * D_;
    const __half* Vg = g_vt + (size_t)bh * D_ * S_;

    auto stageKV = [&](int buf, int kt) {
        uint32_t* Kb = Ks + buf * 64 * AST;
        uint32_t* Vb = Vs + buf * 64 * AST;
#pragma unroll
        for (int i = 0; i < 2; i++) {        // 512 chunks each
            int j = i * 256 + tid;
            int r = j >> 3, c = j & 7;
            cp16(&Kb[r * AST + c * 4], Kg + (size_t)(kt * 64 + r) * D_ + c * 8);
            cp16(&Vb[r * AST + c * 4], Vg + (size_t)r * S_ + kt * 64 + c * 8);
        }
    };

    // prologue: stage Q (128x64 halves) + first K/V tile
#pragma unroll
    for (int i = 0; i < 4; i++) {
        int j = i * 256 + tid;
        int r = j >> 3, c = j & 7;
        cp16(&Qs[r * AST + c * 4], Qg + (size_t)r * D_ + c * 8);
    }
    stageKV(0, 0);
    CP_COMMIT();
    CP_WAIT0();
    __syncthreads();

    // hoist Q fragments into registers (4 kk-groups x {a0a2, a1a3})
    const int qrow0 = w * 16 + g;
    uint2 qf[4][2];
#pragma unroll
    for (int kk = 0; kk < 4; kk++) {
        qf[kk][0] = *reinterpret_cast<const uint2*>(
            &Qs[qrow0 * AST + kk * 8 + 2 * tg]);
        qf[kk][1] = *reinterpret_cast<const uint2*>(
            &Qs[(qrow0 + 8) * AST + kk * 8 + 2 * tg]);
    }

    float yacc[8][4];
#pragma unroll
    for (int ni = 0; ni < 8; ni++)
#pragma unroll
        for (int c = 0; c < 4; c++) yacc[ni][c] = 0.f;

    const int r0 = qbase + w * 16 + g;

    const int nkt = 2 * qt + 2;
    for (int kt = 0; kt < nkt; kt++) {
        if (kt > 0) {
            CP_WAIT0();
            __syncthreads();
        }
        if (kt + 1 < nkt) {
            stageKV((kt + 1) & 1, kt + 1);
            CP_COMMIT();
        }
        uint32_t* Kb = Ks + (kt & 1) * 64 * AST;
        uint32_t* Vb = Vs + (kt & 1) * 64 * AST;

        // ---- S = Q @ K^T : 16 rows x 64 cols, k-depth 64 (4 k16 steps) ----
        float sacc[8][4];
#pragma unroll
        for (int ni = 0; ni < 8; ni++)
#pragma unroll
            for (int c = 0; c < 4; c++) sacc[ni][c] = 0.f;

#pragma unroll
        for (int kk = 0; kk < 4; kk++) {
#pragma unroll
            for (int ni = 0; ni < 8; ni++) {
                uint2 b = *reinterpret_cast<const uint2*>(
                    &Kb[(ni * 8 + g) * AST + kk * 8 + 2 * tg]);
                mma16(sacc[ni],
                      qf[kk][0].x, qf[kk][1].x, qf[kk][0].y, qf[kk][1].y,
                      b.x, b.y);
            }
        }

        // ---- scale, causal mask, relu (keep f32; pack to fp16 in Y) ----
        const bool need_mask = (kt >= 2 * qt);
#pragma unroll
        for (int ni = 0; ni < 8; ni++) {
            int c0 = kt * 64 + ni * 8 + 2 * tg;
            float v0 = fmaxf(sacc[ni][0] * SCALE_, 0.f);
            float v1 = fmaxf(sacc[ni][1] * SCALE_, 0.f);
            float v2 = fmaxf(sacc[ni][2] * SCALE_, 0.f);
            float v3 = fmaxf(sacc[ni][3] * SCALE_, 0.f);
            if (need_mask) {
                if (c0 > r0)         v0 = 0.f;
                if (c0 + 1 > r0)     v1 = 0.f;
                if (c0 > r0 + 8)     v2 = 0.f;
                if (c0 + 1 > r0 + 8) v3 = 0.f;
            }
            sacc[ni][0] = v0; sacc[ni][1] = v1;
            sacc[ni][2] = v2; sacc[ni][3] = v3;
        }

        // ---- Y += P @ V : P packs from sacc into k16 A-frags ----
#pragma unroll
        for (int kk = 0; kk < 4; kk++) {
            uint32_t a0 = packh2(sacc[2 * kk][0],     sacc[2 * kk][1]);
            uint32_t a1 = packh2(sacc[2 * kk][2],     sacc[2 * kk][3]);
            uint32_t a2 = packh2(sacc[2 * kk + 1][0], sacc[2 * kk + 1][1]);
            uint32_t a3 = packh2(sacc[2 * kk + 1][2], sacc[2 * kk + 1][3]);
#pragma unroll
            for (int ni = 0; ni < 8; ni++) {
                uint2 b = *reinterpret_cast<const uint2*>(
                    &Vb[(ni * 8 + g) * AST + kk * 8 + 2 * tg]);
                mma16(yacc[ni], a0, a1, a2, a3, b.x, b.y);
            }
        }
    }

    // ---- write Y to out [B, S, H, D] ----
    const int b = bh / H_, h = bh % H_;
#pragma unroll
    for (int ni = 0; ni < 8; ni++) {
        int d0 = ni * 8 + 2 * tg;
        float2 v0 = make_float2(yacc[ni][0], yacc[ni][1]);
        *reinterpret_cast<float2*>(
            &out[(((size_t)b * S_ + r0) * H_ + h) * D_ + d0]) = v0;
        float2 v1 = make_float2(yacc[ni][2], yacc[ni][3]);
        *reinterpret_cast<float2*>(
            &out[(((size_t)b * S_ + r0 + 8) * H_ + h) * D_ + d0]) = v1;
    }
}

// ---------------------------------------------------------------------------
extern "C" void kernel_launch(void* const* d_in, const int* in_sizes, int n_in,
                              void* d_out, int out_size)
{
    const float* X    = (const float*)d_in[0];   // [4, 2048, 768]
    const float* W    = (const float*)d_in[1];   // [768, 2304]
    const float* bias = (const float*)d_in[2];   // [2304]
    float* out = (float*)d_out;                  // [4, 2048, 768]

    static bool attr_done = false;
    if (!attr_done) {
        cudaFuncSetAttribute(qkv_gemm,
                             cudaFuncAttributeMaxDynamicSharedMemorySize,
                             GEMM_SMEM_BYTES);
        cudaFuncSetAttribute(attn_kernel,
                             cudaFuncAttributeMaxDynamicSharedMemorySize,
                             ATTN_SMEM_BYTES);
        attr_done = true;
    }

    int ngroups = B_ * S_ * E_ / 16;
    cvtx<<<(ngroups + 255) / 256, 256>>>(X, ngroups);
    cvtw<<<dim3(3 * E_ / 32, E_ / 32), dim3(32, 8)>>>(W);

    qkv_gemm<<<dim3(3 * E_ / 128, (B_ * S_) / 128), 256, GEMM_SMEM_BYTES>>>(bias);

    vtrans<<<dim3(S_ / 64, B_ * H_), 256>>>();

    attn_kernel<<<dim3(S_ / 128, B_ * H_), 256, ATTN_SMEM_BYTES>>>(out);
}

// round 8
// speedup vs baseline: 2.0467x; 1.0695x over previous
#include <cuda_runtime.h>
#include <cuda_fp16.h>
#include <cstdint>

// Problem constants
#define B_ 4
#define S_ 2048
#define E_ 768
#define H_ 12
#define D_ 64
#define SCALE_ 0.125f   // 1/sqrt(64)

// Scratch (no cudaMalloc allowed). All layouts natural row-major now
// (ldmatrix handles fragment distribution).
__device__ __align__(16) __half g_x[(size_t)B_ * S_ * E_];         // [m][k]
__device__ __align__(16) __half g_w[(size_t)3 * E_ * E_];          // W^T [n][k]
__device__ __align__(16) __half g_q[(size_t)B_ * H_ * S_ * D_];    // [bh][s][d], pre-scaled by 1/8
__device__ __align__(16) __half g_k[(size_t)B_ * H_ * S_ * D_];    // [bh][s][d]
__device__ __align__(16) __half g_vtmp[(size_t)B_ * H_ * S_ * D_]; // [bh][s][d]
__device__ __align__(16) __half g_vt[(size_t)B_ * H_ * S_ * D_];   // [bh][d][s]

// ---------------------------------------------------------------------------
// helpers
// ---------------------------------------------------------------------------
__device__ __forceinline__ uint32_t packh2(float lo, float hi) {
    __half2 h = __floats2half2_rn(lo, hi);
    return *reinterpret_cast<uint32_t*>(&h);
}

__device__ __forceinline__ void mma16(float c[4],
                                      uint32_t a0, uint32_t a1, uint32_t a2, uint32_t a3,
                                      uint32_t b0, uint32_t b1) {
    asm volatile(
        "mma.sync.aligned.m16n8k16.row.col.f32.f16.f16.f32 "
        "{%0,%1,%2,%3}, {%4,%5,%6,%7}, {%8,%9}, {%0,%1,%2,%3};"
        : "+f"(c[0]), "+f"(c[1]), "+f"(c[2]), "+f"(c[3])
        : "r"(a0), "r"(a1), "r"(a2), "r"(a3), "r"(b0), "r"(b1));
}

__device__ __forceinline__ void ldsm4(uint32_t& r0, uint32_t& r1,
                                      uint32_t& r2, uint32_t& r3, uint32_t addr) {
    asm volatile("ldmatrix.sync.aligned.m8n8.x4.shared.b16 {%0,%1,%2,%3}, [%4];"
                 : "=r"(r0), "=r"(r1), "=r"(r2), "=r"(r3) : "r"(addr));
}

__device__ __forceinline__ void cp16(void* sdst, const void* gsrc) {
    uint32_t a = (uint32_t)__cvta_generic_to_shared(sdst);
    asm volatile("cp.async.cg.shared.global [%0], [%1], 16;"
                 :: "r"(a), "l"(gsrc));
}
#define CP_COMMIT() asm volatile("cp.async.commit_group;")
#define CP_WAIT0()  asm volatile("cp.async.wait_group 0;")

// SMEM row stride: 36 words (64 halves data + 8 pad) -> ldmatrix rows hit
// disjoint 4-bank groups (r*36 mod 32 = 4r), conflict-free.
#define AST 36
#define ROWB (AST * 4)   // 144 bytes per row

// per-lane ldmatrix byte offsets
// A-frag x4: lanes 0-7 rows 0-7 (k-lo), 8-15 rows 8-15 (k-lo),
//            16-23 rows 0-7 (k-hi), 24-31 rows 8-15 (k-hi)
__device__ __forceinline__ uint32_t a_off(int lane) {
    return (uint32_t)((lane & 15) * ROWB + ((lane & 16) ? 16 : 0));
}
// B-frag x4 (2 n-columns): lanes 0-7 rows 0-7 (k-lo), 8-15 rows 0-7 (k-hi),
//                          16-23 rows 8-15 (k-lo), 24-31 rows 8-15 (k-hi)
__device__ __forceinline__ uint32_t b_off(int lane) {
    return (uint32_t)(((lane & 7) + ((lane & 16) >> 1)) * ROWB +
                      ((lane & 8) ? 16 : 0));
}

// ---------------------------------------------------------------------------
// Prep A: X f32 -> g_x fp16 (natural)
// ---------------------------------------------------------------------------
__global__ void cvtx(const float4* __restrict__ X4, int n4)
{
    int i = blockIdx.x * blockDim.x + threadIdx.x;
    if (i >= n4) return;
    float4 v = X4[i];
    uint2 o = make_uint2(packh2(v.x, v.y), packh2(v.z, v.w));
    *reinterpret_cast<uint2*>(g_x + (size_t)i * 4) = o;
}

// ---------------------------------------------------------------------------
// Prep B: W [768][2304] f32 -> g_w = W^T fp16 [2304][768] (natural)
// ---------------------------------------------------------------------------
__global__ void cvtw(const float* __restrict__ W)
{
    __shared__ float t[32][33];
    int n0 = blockIdx.x * 32, k0 = blockIdx.y * 32;
    for (int i = threadIdx.y; i < 32; i += 8)
        t[i][threadIdx.x] = W[(size_t)(k0 + i) * (3 * E_) + n0 + threadIdx.x];
    __syncthreads();
    for (int r = threadIdx.y; r < 32; r += 8) {
        float v = t[threadIdx.x][r];   // = W[k0+tx][n0+r]
        g_w[(size_t)(n0 + r) * E_ + k0 + threadIdx.x] = __float2half_rn(v);
    }
}

// ---------------------------------------------------------------------------
// Prep C (after GEMM): g_vtmp [bh][s][d] -> g_vt [bh][d][s]
// ---------------------------------------------------------------------------
__global__ void vtrans()
{
    __shared__ __half t[64][72];
    int sb = blockIdx.x * 64, bh = blockIdx.y;
    int tid = threadIdx.x;
    const uint32_t* src = reinterpret_cast<const uint32_t*>(
        g_vtmp + ((size_t)bh * S_ + sb) * D_);
#pragma unroll
    for (int i = 0; i < 8; i++) {
        int j = i * 256 + tid;
        int r = j >> 5, c2 = j & 31;
        uint32_t wv = src[r * 32 + c2];
        __half2 h = *reinterpret_cast<__half2*>(&wv);
        t[r][2 * c2]     = __low2half(h);
        t[r][2 * c2 + 1] = __high2half(h);
    }
    __syncthreads();
#pragma unroll
    for (int i = 0; i < 8; i++) {
        int j = i * 256 + tid;
        int d = j >> 5, sl = j & 31;
        __half2 h2 = __halves2half2(t[2 * sl][d], t[2 * sl + 1][d]);
        reinterpret_cast<uint32_t*>(
            g_vt + ((size_t)bh * D_ + d) * S_ + sb)[sl] =
            *reinterpret_cast<uint32_t*>(&h2);
    }
}

// ---------------------------------------------------------------------------
// Kernel 1: QKV projection, fp16 m16n8k16 mma + ldmatrix.
// CTA 128x128, 8 warps (4m x 2n), warp 32x64, BK=64, double-buffered cp.async.
// Epilogue: +bias (Q also *1/8), round fp16, scatter natural layouts.
// ---------------------------------------------------------------------------
#define GEMM_TILE_W (128 * AST)
#define GEMM_SMEM_BYTES (4 * GEMM_TILE_W * 4)

__global__ __launch_bounds__(256, 2) void qkv_gemm(const float* __restrict__ bias)
{
    extern __shared__ uint32_t shg[];
    uint32_t* As = shg;                      // [2][128][36]
    uint32_t* Bs = shg + 2 * GEMM_TILE_W;    // [2][128][36]
    const uint32_t sbase = (uint32_t)__cvta_generic_to_shared(shg);
    const uint32_t boffB = 2 * GEMM_TILE_W * 4;

    const int tid  = threadIdx.x;
    const int lane = tid & 31;
    const int wid  = tid >> 5;
    const int g    = lane >> 2;
    const int tg   = lane & 3;
    const int wm   = wid & 3;     // 4 warp-rows, 32 rows each
    const int wn   = wid >> 2;    // 2 warp-cols, 64 cols each
    const int mbase = blockIdx.y * 128;
    const int nbase = blockIdx.x * 128;

    const uint32_t aoff = a_off(lane);
    const uint32_t boff = b_off(lane);

    float acc[2][8][4];
#pragma unroll
    for (int mi = 0; mi < 2; mi++)
#pragma unroll
        for (int ni = 0; ni < 8; ni++)
#pragma unroll
            for (int c = 0; c < 4; c++) acc[mi][ni][c] = 0.f;

    auto stage = [&](int buf, int k0) {
        uint32_t* Ab = As + buf * GEMM_TILE_W;
        uint32_t* Bb = Bs + buf * GEMM_TILE_W;
#pragma unroll
        for (int i = 0; i < 4; i++) {        // 1024 chunks each
            int j = i * 256 + tid;
            int r = j >> 3, c = j & 7;
            cp16(&Ab[r * AST + c * 4], g_x + (size_t)(mbase + r) * E_ + k0 + c * 8);
            cp16(&Bb[r * AST + c * 4], g_w + (size_t)(nbase + r) * E_ + k0 + c * 8);
        }
    };

    const int NK = E_ / 64;   // 12
    stage(0, 0);
    CP_COMMIT();

    for (int ks = 0; ks < NK; ks++) {
        CP_WAIT0();
        __syncthreads();
        if (ks + 1 < NK) {
            stage((ks + 1) & 1, (ks + 1) * 64);
            CP_COMMIT();
        }
        const uint32_t Aad = sbase + (ks & 1) * (GEMM_TILE_W * 4)
                           + (wm * 32) * ROWB + aoff;
        const uint32_t Bad = sbase + boffB + (ks & 1) * (GEMM_TILE_W * 4)
                           + (wn * 64) * ROWB + boff;

#pragma unroll
        for (int kk = 0; kk < 4; kk++) {
            uint32_t a[2][4];
#pragma unroll
            for (int mi = 0; mi < 2; mi++)
                ldsm4(a[mi][0], a[mi][1], a[mi][2], a[mi][3],
                      Aad + mi * (16 * ROWB) + kk * 32);
#pragma unroll
            for (int n2 = 0; n2 < 4; n2++) {
                uint32_t b0, b1, b2, b3;
                ldsm4(b0, b1, b2, b3, Bad + n2 * (16 * ROWB) + kk * 32);
#pragma unroll
                for (int mi = 0; mi < 2; mi++) {
                    mma16(acc[mi][2 * n2],     a[mi][0], a[mi][1], a[mi][2], a[mi][3], b0, b1);
                    mma16(acc[mi][2 * n2 + 1], a[mi][0], a[mi][1], a[mi][2], a[mi][3], b2, b3);
                }
            }
        }
    }

    // Epilogue: +bias (Q scaled by 1/8), fp16-round, natural scatter
#pragma unroll
    for (int mi = 0; mi < 2; mi++) {
#pragma unroll
        for (int ni = 0; ni < 8; ni++) {
            int n = nbase + wn * 64 + ni * 8 + 2 * tg;   // even
            int which = n / E_;
            int n2 = n - which * E_;
            int h = n2 >> 6, d = n2 & 63;
            float b0 = __ldg(bias + n), b1 = __ldg(bias + n + 1);
            __half* basep = (which == 0) ? g_q : ((which == 1) ? g_k : g_vtmp);
#pragma unroll
            for (int half = 0; half < 2; half++) {
                int m = mbase + wm * 32 + mi * 16 + g + half * 8;
                int bb = m >> 11;
                int ss = m & 2047;
                float va = acc[mi][ni][half * 2 + 0] + b0;
                float vb = acc[mi][ni][half * 2 + 1] + b1;
                if (which == 0) { va *= SCALE_; vb *= SCALE_; }
                uint32_t pw = packh2(va, vb);
                size_t rowbase = (((size_t)bb * H_ + h) * S_ + ss);
                reinterpret_cast<uint32_t*>(basep + rowbase * D_)[d >> 1] = pw;
            }
        }
    }
}

// ---------------------------------------------------------------------------
// Kernel 2: causal ReLU attention, fp16 mma + ldmatrix.
// 8 warps x 16 q-rows, Q frags hoisted, register S->P->Y dataflow,
// double-buffered cp.async K/V. Q pre-scaled by 1/8 so no scale here.
// ---------------------------------------------------------------------------
#define ATTN_SMEM_WORDS (128 * AST + 2 * 64 * AST + 2 * 64 * AST)
#define ATTN_SMEM_BYTES (ATTN_SMEM_WORDS * 4)
#define KOFFB (128 * AST * 4)
#define VOFFB (KOFFB + 2 * 64 * AST * 4)

__global__ __launch_bounds__(256, 2) void attn_kernel(float* __restrict__ out)
{
    extern __shared__ uint32_t sh[];
    uint32_t* Qs = sh;                       // [128][36]
    uint32_t* Ks = Qs + 128 * AST;           // [2][64][36]  K tile [s][d]
    uint32_t* Vs = Ks + 2 * 64 * AST;        // [2][64][36]  V tile [d][s]
    const uint32_t sbase = (uint32_t)__cvta_generic_to_shared(sh);

    const int tid  = threadIdx.x;
    const int lane = tid & 31;
    const int w    = tid >> 5;
    const int g    = lane >> 2;
    const int tg   = lane & 3;
    const int qt   = blockIdx.x;
    const int bh   = blockIdx.y;
    const int qbase = qt * 128;

    const __half* Qg = g_q + ((size_t)bh * S_ + qbase) * D_;
    const __half* Kg = g_k + (size_t)bh * S_ * D_;
    const __half* Vg = g_vt + (size_t)bh * D_ * S_;

    const uint32_t aoff = a_off(lane);
    const uint32_t boff = b_off(lane);

    auto stageKV = [&](int buf, int kt) {
        uint32_t* Kb = Ks + buf * 64 * AST;
        uint32_t* Vb = Vs + buf * 64 * AST;
#pragma unroll
        for (int i = 0; i < 2; i++) {        // 512 chunks each
            int j = i * 256 + tid;
            int r = j >> 3, c = j & 7;
            cp16(&Kb[r * AST + c * 4], Kg + (size_t)(kt * 64 + r) * D_ + c * 8);
            cp16(&Vb[r * AST + c * 4], Vg + (size_t)r * S_ + kt * 64 + c * 8);
        }
    };

    // prologue: stage Q (128x64) + first K/V tile
#pragma unroll
    for (int i = 0; i < 4; i++) {
        int j = i * 256 + tid;
        int r = j >> 3, c = j & 7;
        cp16(&Qs[r * AST + c * 4], Qg + (size_t)r * D_ + c * 8);
    }
    stageKV(0, 0);
    CP_COMMIT();
    CP_WAIT0();
    __syncthreads();

    // hoist Q fragments (4 k16 groups)
    uint32_t qf[4][4];
    {
        const uint32_t Qad = sbase + (w * 16) * ROWB + aoff;
#pragma unroll
        for (int kk = 0; kk < 4; kk++)
            ldsm4(qf[kk][0], qf[kk][1], qf[kk][2], qf[kk][3], Qad + kk * 32);
    }

    float yacc[8][4];
#pragma unroll
    for (int ni = 0; ni < 8; ni++)
#pragma unroll
        for (int c = 0; c < 4; c++) yacc[ni][c] = 0.f;

    const int r0 = qbase + w * 16 + g;

    const int nkt = 2 * qt + 2;
    for (int kt = 0; kt < nkt; kt++) {
        if (kt > 0) {
            CP_WAIT0();
            __syncthreads();
        }
        if (kt + 1 < nkt) {
            stageKV((kt + 1) & 1, kt + 1);
            CP_COMMIT();
        }
        const uint32_t Kad = sbase + KOFFB + (kt & 1) * (64 * AST * 4) + boff;
        const uint32_t Vad = sbase + VOFFB + (kt & 1) * (64 * AST * 4) + boff;

        // ---- S = Q @ K^T : 16 rows x 64 cols, k-depth 64 ----
        float sacc[8][4];
#pragma unroll
        for (int ni = 0; ni < 8; ni++)
#pragma unroll
            for (int c = 0; c < 4; c++) sacc[ni][c] = 0.f;

#pragma unroll
        for (int kk = 0; kk < 4; kk++) {
#pragma unroll
            for (int n2 = 0; n2 < 4; n2++) {
                uint32_t b0, b1, b2, b3;
                ldsm4(b0, b1, b2, b3, Kad + n2 * (16 * ROWB) + kk * 32);
                mma16(sacc[2 * n2],     qf[kk][0], qf[kk][1], qf[kk][2], qf[kk][3], b0, b1);
                mma16(sacc[2 * n2 + 1], qf[kk][0], qf[kk][1], qf[kk][2], qf[kk][3], b2, b3);
            }
        }

        // ---- causal mask + relu (scale pre-folded into Q) ----
        if (kt >= 2 * qt) {
#pragma unroll
            for (int ni = 0; ni < 8; ni++) {
                int c0 = kt * 64 + ni * 8 + 2 * tg;
                float v0 = fmaxf(sacc[ni][0], 0.f);
                float v1 = fmaxf(sacc[ni][1], 0.f);
                float v2 = fmaxf(sacc[ni][2], 0.f);
                float v3 = fmaxf(sacc[ni][3], 0.f);
                if (c0 > r0)         v0 = 0.f;
                if (c0 + 1 > r0)     v1 = 0.f;
                if (c0 > r0 + 8)     v2 = 0.f;
                if (c0 + 1 > r0 + 8) v3 = 0.f;
                sacc[ni][0] = v0; sacc[ni][1] = v1;
                sacc[ni][2] = v2; sacc[ni][3] = v3;
            }
        } else {
#pragma unroll
            for (int ni = 0; ni < 8; ni++) {
                sacc[ni][0] = fmaxf(sacc[ni][0], 0.f);
                sacc[ni][1] = fmaxf(sacc[ni][1], 0.f);
                sacc[ni][2] = fmaxf(sacc[ni][2], 0.f);
                sacc[ni][3] = fmaxf(sacc[ni][3], 0.f);
            }
        }

        // ---- Y += P @ V : P packs from sacc into k16 A-frags ----
#pragma unroll
        for (int kk = 0; kk < 4; kk++) {
            uint32_t a0 = packh2(sacc[2 * kk][0],     sacc[2 * kk][1]);
            uint32_t a1 = packh2(sacc[2 * kk][2],     sacc[2 * kk][3]);
            uint32_t a2 = packh2(sacc[2 * kk + 1][0], sacc[2 * kk + 1][1]);
            uint32_t a3 = packh2(sacc[2 * kk + 1][2], sacc[2 * kk + 1][3]);
#pragma unroll
            for (int n2 = 0; n2 < 4; n2++) {
                uint32_t b0, b1, b2, b3;
                ldsm4(b0, b1, b2, b3, Vad + n2 * (16 * ROWB) + kk * 32);
                mma16(yacc[2 * n2],     a0, a1, a2, a3, b0, b1);
                mma16(yacc[2 * n2 + 1], a0, a1, a2, a3, b2, b3);
            }
        }
    }

    // ---- write Y to out [B, S, H, D] ----
    const int b = bh / H_, h = bh % H_;
#pragma unroll
    for (int ni = 0; ni < 8; ni++) {
        int d0 = ni * 8 + 2 * tg;
        float2 v0 = make_float2(yacc[ni][0], yacc[ni][1]);
        *reinterpret_cast<float2*>(
            &out[(((size_t)b * S_ + r0) * H_ + h) * D_ + d0]) = v0;
        float2 v1 = make_float2(yacc[ni][2], yacc[ni][3]);
        *reinterpret_cast<float2*>(
            &out[(((size_t)b * S_ + r0 + 8) * H_ + h) * D_ + d0]) = v1;
    }
}

// ---------------------------------------------------------------------------
extern "C" void kernel_launch(void* const* d_in, const int* in_sizes, int n_in,
                              void* d_out, int out_size)
{
    const float* X    = (const float*)d_in[0];   // [4, 2048, 768]
    const float* W    = (const float*)d_in[1];   // [768, 2304]
    const float* bias = (const float*)d_in[2];   // [2304]
    float* out = (float*)d_out;                  // [4, 2048, 768]

    static bool attr_done = false;
    if (!attr_done) {
        cudaFuncSetAttribute(qkv_gemm,
                             cudaFuncAttributeMaxDynamicSharedMemorySize,
                             GEMM_SMEM_BYTES);
        cudaFuncSetAttribute(attn_kernel,
                             cudaFuncAttributeMaxDynamicSharedMemorySize,
                             ATTN_SMEM_BYTES);
        attr_done = true;
    }

    int n4 = B_ * S_ * E_ / 4;
    cvtx<<<(n4 + 255) / 256, 256>>>((const float4*)X, n4);
    cvtw<<<dim3(3 * E_ / 32, E_ / 32), dim3(32, 8)>>>(W);

    qkv_gemm<<<dim3(3 * E_ / 128, (B_ * S_) / 128), 256, GEMM_SMEM_BYTES>>>(bias);

    vtrans<<<dim3(S_ / 64, B_ * H_), 256>>>();

    attn_kernel<<<dim3(S_ / 128, B_ * H_), 256, ATTN_SMEM_BYTES>>>(out);
}

// round 9
// speedup vs baseline: 2.1419x; 1.0465x over previous
#include <cuda_runtime.h>
#include <cuda_fp16.h>
#include <cstdint>

// Problem constants
#define B_ 4
#define S_ 2048
#define E_ 768
#define H_ 12
#define D_ 64
#define SCALE_ 0.125f   // 1/sqrt(64)

// Scratch (no cudaMalloc allowed). Natural row-major layouts.
__device__ __align__(16) __half g_x[(size_t)B_ * S_ * E_];         // [m][k]
__device__ __align__(16) __half g_w[(size_t)3 * E_ * E_];          // W^T [n][k]
__device__ __align__(16) __half g_q[(size_t)B_ * H_ * S_ * D_];    // [bh][s][d], pre-scaled 1/8
__device__ __align__(16) __half g_k[(size_t)B_ * H_ * S_ * D_];    // [bh][s][d]
__device__ __align__(16) __half g_vtmp[(size_t)B_ * H_ * S_ * D_]; // [bh][s][d]
__device__ __align__(16) __half g_vt[(size_t)B_ * H_ * S_ * D_];   // [bh][d][s]

// ---------------------------------------------------------------------------
// helpers
// ---------------------------------------------------------------------------
__device__ __forceinline__ uint32_t packh2(float lo, float hi) {
    __half2 h = __floats2half2_rn(lo, hi);
    return *reinterpret_cast<uint32_t*>(&h);
}

__device__ __forceinline__ uint32_t hmax2z(uint32_t x) {
    uint32_t r;
    asm("max.f16x2 %0, %1, %2;" : "=r"(r) : "r"(x), "r"(0u));
    return r;
}

__device__ __forceinline__ void mma16(float c[4],
                                      uint32_t a0, uint32_t a1, uint32_t a2, uint32_t a3,
                                      uint32_t b0, uint32_t b1) {
    asm volatile(
        "mma.sync.aligned.m16n8k16.row.col.f32.f16.f16.f32 "
        "{%0,%1,%2,%3}, {%4,%5,%6,%7}, {%8,%9}, {%0,%1,%2,%3};"
        : "+f"(c[0]), "+f"(c[1]), "+f"(c[2]), "+f"(c[3])
        : "r"(a0), "r"(a1), "r"(a2), "r"(a3), "r"(b0), "r"(b1));
}

__device__ __forceinline__ void ldsm4(uint32_t& r0, uint32_t& r1,
                                      uint32_t& r2, uint32_t& r3, uint32_t addr) {
    asm volatile("ldmatrix.sync.aligned.m8n8.x4.shared.b16 {%0,%1,%2,%3}, [%4];"
                 : "=r"(r0), "=r"(r1), "=r"(r2), "=r"(r3) : "r"(addr));
}

__device__ __forceinline__ void cp16(void* sdst, const void* gsrc) {
    uint32_t a = (uint32_t)__cvta_generic_to_shared(sdst);
    asm volatile("cp.async.cg.shared.global [%0], [%1], 16;"
                 :: "r"(a), "l"(gsrc));
}
#define CP_COMMIT() asm volatile("cp.async.commit_group;")
#define CP_WAIT0()  asm volatile("cp.async.wait_group 0;")

// SMEM row strides giving conflict-free ldmatrix (4-bank groups disjoint):
#define AST 36              // 64-half rows: 36 words (4r mod 32 groups)
#define ROWB (AST * 4)      // 144 B
#define VST 68              // 128-half rows: 68 words (4r mod 32 groups)
#define VROWB (VST * 4)     // 272 B

// per-lane ldmatrix byte offsets
__device__ __forceinline__ uint32_t a_off(int lane) {          // A-frag x4
    return (uint32_t)((lane & 15) * ROWB + ((lane & 16) ? 16 : 0));
}
__device__ __forceinline__ uint32_t b_offs(int lane, int rowb) { // B-frag x4
    return (uint32_t)(((lane & 7) + ((lane & 16) >> 1)) * rowb +
                      ((lane & 8) ? 16 : 0));
}

// ---------------------------------------------------------------------------
// Prep A: X f32 -> g_x fp16
// ---------------------------------------------------------------------------
__global__ void cvtx(const float4* __restrict__ X4, int n4)
{
    int i = blockIdx.x * blockDim.x + threadIdx.x;
    if (i >= n4) return;
    float4 v = X4[i];
    uint2 o = make_uint2(packh2(v.x, v.y), packh2(v.z, v.w));
    *reinterpret_cast<uint2*>(g_x + (size_t)i * 4) = o;
}

// ---------------------------------------------------------------------------
// Prep B: W [768][2304] f32 -> g_w = W^T fp16 [2304][768]
// ---------------------------------------------------------------------------
__global__ void cvtw(const float* __restrict__ W)
{
    __shared__ float t[32][33];
    int n0 = blockIdx.x * 32, k0 = blockIdx.y * 32;
    for (int i = threadIdx.y; i < 32; i += 8)
        t[i][threadIdx.x] = W[(size_t)(k0 + i) * (3 * E_) + n0 + threadIdx.x];
    __syncthreads();
    for (int r = threadIdx.y; r < 32; r += 8) {
        float v = t[threadIdx.x][r];
        g_w[(size_t)(n0 + r) * E_ + k0 + threadIdx.x] = __float2half_rn(v);
    }
}

// ---------------------------------------------------------------------------
// Prep C: g_vtmp [bh][s][d] -> g_vt [bh][d][s]  (stride-66 smem, low conflict)
// ---------------------------------------------------------------------------
__global__ void vtrans()
{
    __shared__ __half t[64][66];
    int sb = blockIdx.x * 64, bh = blockIdx.y;
    int tid = threadIdx.x;
    const uint32_t* src = reinterpret_cast<const uint32_t*>(
        g_vtmp + ((size_t)bh * S_ + sb) * D_);
#pragma unroll
    for (int i = 0; i < 8; i++) {
        int j = i * 256 + tid;
        int r = j >> 5, c2 = j & 31;
        uint32_t wv = src[r * 32 + c2];
        *reinterpret_cast<__half2*>(&t[r][2 * c2]) =
            *reinterpret_cast<__half2*>(&wv);
    }
    __syncthreads();
#pragma unroll
    for (int i = 0; i < 8; i++) {
        int j = i * 256 + tid;
        int d = j >> 5, sl = j & 31;
        __half2 h2 = __halves2half2(t[2 * sl][d], t[2 * sl + 1][d]);
        reinterpret_cast<uint32_t*>(
            g_vt + ((size_t)bh * D_ + d) * S_ + sb)[sl] =
            *reinterpret_cast<uint32_t*>(&h2);
    }
}

// ---------------------------------------------------------------------------
// Kernel 1: QKV projection (unchanged from round 8 — known good).
// ---------------------------------------------------------------------------
#define GEMM_TILE_W (128 * AST)
#define GEMM_SMEM_BYTES (4 * GEMM_TILE_W * 4)

__global__ __launch_bounds__(256, 2) void qkv_gemm(const float* __restrict__ bias)
{
    extern __shared__ uint32_t shg[];
    uint32_t* As = shg;
    uint32_t* Bs = shg + 2 * GEMM_TILE_W;
    const uint32_t sbase = (uint32_t)__cvta_generic_to_shared(shg);
    const uint32_t boffB = 2 * GEMM_TILE_W * 4;

    const int tid  = threadIdx.x;
    const int lane = tid & 31;
    const int wid  = tid >> 5;
    const int g    = lane >> 2;
    const int tg   = lane & 3;
    const int wm   = wid & 3;
    const int wn   = wid >> 2;
    const int mbase = blockIdx.y * 128;
    const int nbase = blockIdx.x * 128;

    const uint32_t aoff = a_off(lane);
    const uint32_t boff = b_offs(lane, ROWB);

    float acc[2][8][4];
#pragma unroll
    for (int mi = 0; mi < 2; mi++)
#pragma unroll
        for (int ni = 0; ni < 8; ni++)
#pragma unroll
            for (int c = 0; c < 4; c++) acc[mi][ni][c] = 0.f;

    auto stage = [&](int buf, int k0) {
        uint32_t* Ab = As + buf * GEMM_TILE_W;
        uint32_t* Bb = Bs + buf * GEMM_TILE_W;
#pragma unroll
        for (int i = 0; i < 4; i++) {
            int j = i * 256 + tid;
            int r = j >> 3, c = j & 7;
            cp16(&Ab[r * AST + c * 4], g_x + (size_t)(mbase + r) * E_ + k0 + c * 8);
            cp16(&Bb[r * AST + c * 4], g_w + (size_t)(nbase + r) * E_ + k0 + c * 8);
        }
    };

    const int NK = E_ / 64;   // 12
    stage(0, 0);
    CP_COMMIT();

    for (int ks = 0; ks < NK; ks++) {
        CP_WAIT0();
        __syncthreads();
        if (ks + 1 < NK) {
            stage((ks + 1) & 1, (ks + 1) * 64);
            CP_COMMIT();
        }
        const uint32_t Aad = sbase + (ks & 1) * (GEMM_TILE_W * 4)
                           + (wm * 32) * ROWB + aoff;
        const uint32_t Bad = sbase + boffB + (ks & 1) * (GEMM_TILE_W * 4)
                           + (wn * 64) * ROWB + boff;

#pragma unroll
        for (int kk = 0; kk < 4; kk++) {
            uint32_t a[2][4];
#pragma unroll
            for (int mi = 0; mi < 2; mi++)
                ldsm4(a[mi][0], a[mi][1], a[mi][2], a[mi][3],
                      Aad + mi * (16 * ROWB) + kk * 32);
#pragma unroll
            for (int n2 = 0; n2 < 4; n2++) {
                uint32_t b0, b1, b2, b3;
                ldsm4(b0, b1, b2, b3, Bad + n2 * (16 * ROWB) + kk * 32);
#pragma unroll
                for (int mi = 0; mi < 2; mi++) {
                    mma16(acc[mi][2 * n2],     a[mi][0], a[mi][1], a[mi][2], a[mi][3], b0, b1);
                    mma16(acc[mi][2 * n2 + 1], a[mi][0], a[mi][1], a[mi][2], a[mi][3], b2, b3);
                }
            }
        }
    }

#pragma unroll
    for (int mi = 0; mi < 2; mi++) {
#pragma unroll
        for (int ni = 0; ni < 8; ni++) {
            int n = nbase + wn * 64 + ni * 8 + 2 * tg;
            int which = n / E_;
            int n2 = n - which * E_;
            int h = n2 >> 6, d = n2 & 63;
            float b0 = __ldg(bias + n), b1 = __ldg(bias + n + 1);
            __half* basep = (which == 0) ? g_q : ((which == 1) ? g_k : g_vtmp);
#pragma unroll
            for (int half = 0; half < 2; half++) {
                int m = mbase + wm * 32 + mi * 16 + g + half * 8;
                int bb = m >> 11;
                int ss = m & 2047;
                float va = acc[mi][ni][half * 2 + 0] + b0;
                float vb = acc[mi][ni][half * 2 + 1] + b1;
                if (which == 0) { va *= SCALE_; vb *= SCALE_; }
                uint32_t pw = packh2(va, vb);
                size_t rowbase = (((size_t)bb * H_ + h) * S_ + ss);
                reinterpret_cast<uint32_t*>(basep + rowbase * D_)[d >> 1] = pw;
            }
        }
    }
}

// ---------------------------------------------------------------------------
// Kernel 2: causal ReLU attention, fp16 mma + ldmatrix.
// K-super-tile 128 (two 64-sub-tiles per stage -> half the barriers),
// balanced 1D work order (heavy/light interleave), register S->P->Y.
// ---------------------------------------------------------------------------
#define QBYTES (128 * AST * 4)            // 18432
#define KBUF   (128 * AST * 4)            // 18432 (128 s-rows x 144B)
#define VBUF   (64 * VST * 4)             // 17408 (64 d-rows x 272B)
#define KOFFB  QBYTES
#define VOFFB  (KOFFB + 2 * KBUF)
#define ATTN_SMEM_BYTES (VOFFB + 2 * VBUF)   // 90112

__global__ __launch_bounds__(256, 2) void attn_kernel(float* __restrict__ out)
{
    extern __shared__ uint32_t sh[];
    uint32_t* Qs = sh;                        // [128][36]
    uint32_t* Ks = Qs + 128 * AST;            // [2][128][36]  K [s][d]
    uint32_t* Vs = Ks + 2 * 128 * AST;        // [2][64][68]   V [d][s]
    const uint32_t sbase = (uint32_t)__cvta_generic_to_shared(sh);

    const int tid  = threadIdx.x;
    const int lane = tid & 31;
    const int w    = tid >> 5;
    const int g    = lane >> 2;
    const int tg   = lane & 3;

    // balanced mapping: within each bh's 16 ids, interleave heavy/light
    const int id = blockIdx.x;
    const int bh = id >> 4;
    const int j  = id & 15;
    const int qt = (j & 1) ? ((j - 1) >> 1) : (15 - (j >> 1));
    const int qbase = qt * 128;

    const __half* Qg = g_q + ((size_t)bh * S_ + qbase) * D_;
    const __half* Kg = g_k + (size_t)bh * S_ * D_;
    const __half* Vg = g_vt + (size_t)bh * D_ * S_;

    const uint32_t aoff  = a_off(lane);
    const uint32_t boffK = b_offs(lane, ROWB);
    const uint32_t boffV = b_offs(lane, VROWB);

    // stage a 128-s super-tile of K and V
    auto stageKV = [&](int buf, int kt2) {
        uint32_t* Kb = Ks + buf * (128 * AST);
        uint32_t* Vb = Vs + buf * (64 * VST);
#pragma unroll
        for (int i = 0; i < 4; i++) {         // K: 128 rows x 8 chunks
            int jj = i * 256 + tid;
            int r = jj >> 3, c = jj & 7;
            cp16(&Kb[r * AST + c * 4], Kg + (size_t)(kt2 * 128 + r) * D_ + c * 8);
        }
#pragma unroll
        for (int i = 0; i < 4; i++) {         // V: 64 rows x 16 chunks
            int jj = i * 256 + tid;
            int r = jj >> 4, c = jj & 15;
            cp16(&Vb[r * VST + c * 4], Vg + (size_t)r * S_ + kt2 * 128 + c * 8);
        }
    };

    // prologue: stage Q + first super-tile
#pragma unroll
    for (int i = 0; i < 4; i++) {
        int jj = i * 256 + tid;
        int r = jj >> 3, c = jj & 7;
        cp16(&Qs[r * AST + c * 4], Qg + (size_t)r * D_ + c * 8);
    }
    stageKV(0, 0);
    CP_COMMIT();
    CP_WAIT0();
    __syncthreads();

    // hoist Q fragments (4 k16 groups)
    uint32_t qf[4][4];
    {
        const uint32_t Qad = sbase + (w * 16) * ROWB + aoff;
#pragma unroll
        for (int kk = 0; kk < 4; kk++)
            ldsm4(qf[kk][0], qf[kk][1], qf[kk][2], qf[kk][3], Qad + kk * 32);
    }

    float yacc[8][4];
#pragma unroll
    for (int ni = 0; ni < 8; ni++)
#pragma unroll
        for (int c = 0; c < 4; c++) yacc[ni][c] = 0.f;

    const int r0 = qbase + w * 16 + g;
    const int nkt2 = qt + 1;

    for (int kt2 = 0; kt2 < nkt2; kt2++) {
        if (kt2 > 0) {
            CP_WAIT0();
            __syncthreads();
        }
        if (kt2 + 1 < nkt2) {
            stageKV((kt2 + 1) & 1, kt2 + 1);
            CP_COMMIT();
        }
        const int buf = kt2 & 1;
        const uint32_t Kbase = sbase + KOFFB + buf * KBUF + boffK;
        const uint32_t Vbase = sbase + VOFFB + buf * VBUF + boffV;
        const bool diag = (kt2 == qt);   // both sub-tiles need masking

#pragma unroll
        for (int st = 0; st < 2; st++) {
            const uint32_t Kad = Kbase + st * (64 * ROWB);
            const uint32_t Vad = Vbase + st * 128;

            // ---- S = Q @ K^T : 16 rows x 64 cols ----
            float sacc[8][4];
#pragma unroll
            for (int ni = 0; ni < 8; ni++)
#pragma unroll
                for (int c = 0; c < 4; c++) sacc[ni][c] = 0.f;

#pragma unroll
            for (int kk = 0; kk < 4; kk++) {
#pragma unroll
                for (int n2 = 0; n2 < 4; n2++) {
                    uint32_t b0, b1, b2, b3;
                    ldsm4(b0, b1, b2, b3, Kad + n2 * (16 * ROWB) + kk * 32);
                    mma16(sacc[2 * n2],     qf[kk][0], qf[kk][1], qf[kk][2], qf[kk][3], b0, b1);
                    mma16(sacc[2 * n2 + 1], qf[kk][0], qf[kk][1], qf[kk][2], qf[kk][3], b2, b3);
                }
            }

            // ---- relu (+ mask on diagonal super-tile), pack to A-frags ----
            uint32_t pa[4][4];
            if (diag) {
                const int ktAbs = 2 * kt2 + st;
#pragma unroll
                for (int ni = 0; ni < 8; ni++) {
                    int c0 = ktAbs * 64 + ni * 8 + 2 * tg;
                    float v0 = fmaxf(sacc[ni][0], 0.f);
                    float v1 = fmaxf(sacc[ni][1], 0.f);
                    float v2 = fmaxf(sacc[ni][2], 0.f);
                    float v3 = fmaxf(sacc[ni][3], 0.f);
                    if (c0 > r0)         v0 = 0.f;
                    if (c0 + 1 > r0)     v1 = 0.f;
                    if (c0 > r0 + 8)     v2 = 0.f;
                    if (c0 + 1 > r0 + 8) v3 = 0.f;
                    sacc[ni][0] = v0; sacc[ni][1] = v1;
                    sacc[ni][2] = v2; sacc[ni][3] = v3;
                }
#pragma unroll
                for (int kk = 0; kk < 4; kk++) {
                    pa[kk][0] = packh2(sacc[2 * kk][0],     sacc[2 * kk][1]);
                    pa[kk][1] = packh2(sacc[2 * kk][2],     sacc[2 * kk][3]);
                    pa[kk][2] = packh2(sacc[2 * kk + 1][0], sacc[2 * kk + 1][1]);
                    pa[kk][3] = packh2(sacc[2 * kk + 1][2], sacc[2 * kk + 1][3]);
                }
            } else {
#pragma unroll
                for (int kk = 0; kk < 4; kk++) {
                    pa[kk][0] = hmax2z(packh2(sacc[2 * kk][0],     sacc[2 * kk][1]));
                    pa[kk][1] = hmax2z(packh2(sacc[2 * kk][2],     sacc[2 * kk][3]));
                    pa[kk][2] = hmax2z(packh2(sacc[2 * kk + 1][0], sacc[2 * kk + 1][1]));
                    pa[kk][3] = hmax2z(packh2(sacc[2 * kk + 1][2], sacc[2 * kk + 1][3]));
                }
            }

            // ---- Y += P @ V ----
#pragma unroll
            for (int kk = 0; kk < 4; kk++) {
#pragma unroll
                for (int n2 = 0; n2 < 4; n2++) {
                    uint32_t b0, b1, b2, b3;
                    ldsm4(b0, b1, b2, b3, Vad + n2 * (16 * VROWB) + kk * 32);
                    mma16(yacc[2 * n2],     pa[kk][0], pa[kk][1], pa[kk][2], pa[kk][3], b0, b1);
                    mma16(yacc[2 * n2 + 1], pa[kk][0], pa[kk][1], pa[kk][2], pa[kk][3], b2, b3);
                }
            }
        }
    }

    // ---- write Y to out [B, S, H, D] ----
    const int b = bh / H_, h = bh % H_;
#pragma unroll
    for (int ni = 0; ni < 8; ni++) {
        int d0 = ni * 8 + 2 * tg;
        float2 v0 = make_float2(yacc[ni][0], yacc[ni][1]);
        *reinterpret_cast<float2*>(
            &out[(((size_t)b * S_ + r0) * H_ + h) * D_ + d0]) = v0;
        float2 v1 = make_float2(yacc[ni][2], yacc[ni][3]);
        *reinterpret_cast<float2*>(
            &out[(((size_t)b * S_ + r0 + 8) * H_ + h) * D_ + d0]) = v1;
    }
}

// ---------------------------------------------------------------------------
extern "C" void kernel_launch(void* const* d_in, const int* in_sizes, int n_in,
                              void* d_out, int out_size)
{
    const float* X    = (const float*)d_in[0];   // [4, 2048, 768]
    const float* W    = (const float*)d_in[1];   // [768, 2304]
    const float* bias = (const float*)d_in[2];   // [2304]
    float* out = (float*)d_out;                  // [4, 2048, 768]

    static bool attr_done = false;
    if (!attr_done) {
        cudaFuncSetAttribute(qkv_gemm,
                             cudaFuncAttributeMaxDynamicSharedMemorySize,
                             GEMM_SMEM_BYTES);
        cudaFuncSetAttribute(attn_kernel,
                             cudaFuncAttributeMaxDynamicSharedMemorySize,
                             ATTN_SMEM_BYTES);
        attr_done = true;
    }

    int n4 = B_ * S_ * E_ / 4;
    cvtx<<<(n4 + 255) / 256, 256>>>((const float4*)X, n4);
    cvtw<<<dim3(3 * E_ / 32, E_ / 32), dim3(32, 8)>>>(W);

    qkv_gemm<<<dim3(3 * E_ / 128, (B_ * S_) / 128), 256, GEMM_SMEM_BYTES>>>(bias);

    vtrans<<<dim3(S_ / 64, B_ * H_), 256>>>();

    attn_kernel<<<(S_ / 128) * B_ * H_, 256, ATTN_SMEM_BYTES>>>(out);
}

// round 10
// speedup vs baseline: 2.2002x; 1.0272x over previous
#include <cuda_runtime.h>
#include <cuda_fp16.h>
#include <cstdint>

// Problem constants
#define B_ 4
#define S_ 2048
#define E_ 768
#define H_ 12
#define D_ 64
#define SCALE_ 0.125f   // 1/sqrt(64)

// Scratch (no cudaMalloc allowed). Natural row-major layouts.
__device__ __align__(16) __half g_x[(size_t)B_ * S_ * E_];         // [m][k]
__device__ __align__(16) __half g_w[(size_t)3 * E_ * E_];          // W^T [n][k]
__device__ __align__(16) __half g_q[(size_t)B_ * H_ * S_ * D_];    // [bh][s][d], pre-scaled 1/8
__device__ __align__(16) __half g_k[(size_t)B_ * H_ * S_ * D_];    // [bh][s][d]
__device__ __align__(16) __half g_v[(size_t)B_ * H_ * S_ * D_];    // [bh][s][d]

// ---------------------------------------------------------------------------
// helpers
// ---------------------------------------------------------------------------
__device__ __forceinline__ uint32_t packh2(float lo, float hi) {
    __half2 h = __floats2half2_rn(lo, hi);
    return *reinterpret_cast<uint32_t*>(&h);
}

__device__ __forceinline__ uint32_t hmax2z(uint32_t x) {
    uint32_t r;
    asm("max.f16x2 %0, %1, %2;" : "=r"(r) : "r"(x), "r"(0u));
    return r;
}

__device__ __forceinline__ void mma16(float c[4],
                                      uint32_t a0, uint32_t a1, uint32_t a2, uint32_t a3,
                                      uint32_t b0, uint32_t b1) {
    asm volatile(
        "mma.sync.aligned.m16n8k16.row.col.f32.f16.f16.f32 "
        "{%0,%1,%2,%3}, {%4,%5,%6,%7}, {%8,%9}, {%0,%1,%2,%3};"
        : "+f"(c[0]), "+f"(c[1]), "+f"(c[2]), "+f"(c[3])
        : "r"(a0), "r"(a1), "r"(a2), "r"(a3), "r"(b0), "r"(b1));
}

__device__ __forceinline__ void ldsm4(uint32_t& r0, uint32_t& r1,
                                      uint32_t& r2, uint32_t& r3, uint32_t addr) {
    asm volatile("ldmatrix.sync.aligned.m8n8.x4.shared.b16 {%0,%1,%2,%3}, [%4];"
                 : "=r"(r0), "=r"(r1), "=r"(r2), "=r"(r3) : "r"(addr));
}

__device__ __forceinline__ void ldsm4t(uint32_t& r0, uint32_t& r1,
                                       uint32_t& r2, uint32_t& r3, uint32_t addr) {
    asm volatile("ldmatrix.sync.aligned.m8n8.x4.trans.shared.b16 {%0,%1,%2,%3}, [%4];"
                 : "=r"(r0), "=r"(r1), "=r"(r2), "=r"(r3) : "r"(addr));
}

__device__ __forceinline__ void cp16(void* sdst, const void* gsrc) {
    uint32_t a = (uint32_t)__cvta_generic_to_shared(sdst);
    asm volatile("cp.async.cg.shared.global [%0], [%1], 16;"
                 :: "r"(a), "l"(gsrc));
}
#define CP_COMMIT() asm volatile("cp.async.commit_group;")
#define CP_WAIT0()  asm volatile("cp.async.wait_group 0;")

// SMEM row stride for 64-half rows: 36 words -> ldmatrix rows hit disjoint
// 4-bank groups (4r mod 32), conflict-free.
#define AST 36
#define ROWB (AST * 4)   // 144 B

// per-lane ldmatrix byte offsets
// A-frag / V-trans-frag x4: lanes 0-15 rows 0-15 (+0B), lanes 16-31 rows 0-15 (+16B)
__device__ __forceinline__ uint32_t a_off(int lane) {
    return (uint32_t)((lane & 15) * ROWB + ((lane & 16) ? 16 : 0));
}
// B-frag (non-trans) x4: lanes 0-7 rows 0-7 (+0B), 8-15 rows 0-7 (+16B),
//                        16-23 rows 8-15 (+0B), 24-31 rows 8-15 (+16B)
__device__ __forceinline__ uint32_t b_off(int lane) {
    return (uint32_t)(((lane & 7) + ((lane & 16) >> 1)) * ROWB +
                      ((lane & 8) ? 16 : 0));
}

// ---------------------------------------------------------------------------
// Prep A: X f32 -> g_x fp16
// ---------------------------------------------------------------------------
__global__ void cvtx(const float4* __restrict__ X4, int n4)
{
    int i = blockIdx.x * blockDim.x + threadIdx.x;
    if (i >= n4) return;
    float4 v = X4[i];
    uint2 o = make_uint2(packh2(v.x, v.y), packh2(v.z, v.w));
    *reinterpret_cast<uint2*>(g_x + (size_t)i * 4) = o;
}

// ---------------------------------------------------------------------------
// Prep B: W [768][2304] f32 -> g_w = W^T fp16 [2304][768]
// ---------------------------------------------------------------------------
__global__ void cvtw(const float* __restrict__ W)
{
    __shared__ float t[32][33];
    int n0 = blockIdx.x * 32, k0 = blockIdx.y * 32;
    for (int i = threadIdx.y; i < 32; i += 8)
        t[i][threadIdx.x] = W[(size_t)(k0 + i) * (3 * E_) + n0 + threadIdx.x];
    __syncthreads();
    for (int r = threadIdx.y; r < 32; r += 8) {
        float v = t[threadIdx.x][r];
        g_w[(size_t)(n0 + r) * E_ + k0 + threadIdx.x] = __float2half_rn(v);
    }
}

// ---------------------------------------------------------------------------
// Kernel 1: QKV projection (round-8 config — known good).
// ---------------------------------------------------------------------------
#define GEMM_TILE_W (128 * AST)
#define GEMM_SMEM_BYTES (4 * GEMM_TILE_W * 4)

__global__ __launch_bounds__(256, 2) void qkv_gemm(const float* __restrict__ bias)
{
    extern __shared__ uint32_t shg[];
    uint32_t* As = shg;
    uint32_t* Bs = shg + 2 * GEMM_TILE_W;
    const uint32_t sbase = (uint32_t)__cvta_generic_to_shared(shg);
    const uint32_t boffB = 2 * GEMM_TILE_W * 4;

    const int tid  = threadIdx.x;
    const int lane = tid & 31;
    const int wid  = tid >> 5;
    const int g    = lane >> 2;
    const int tg   = lane & 3;
    const int wm   = wid & 3;
    const int wn   = wid >> 2;
    const int mbase = blockIdx.y * 128;
    const int nbase = blockIdx.x * 128;

    const uint32_t aoff = a_off(lane);
    const uint32_t boff = b_off(lane);

    float acc[2][8][4];
#pragma unroll
    for (int mi = 0; mi < 2; mi++)
#pragma unroll
        for (int ni = 0; ni < 8; ni++)
#pragma unroll
            for (int c = 0; c < 4; c++) acc[mi][ni][c] = 0.f;

    auto stage = [&](int buf, int k0) {
        uint32_t* Ab = As + buf * GEMM_TILE_W;
        uint32_t* Bb = Bs + buf * GEMM_TILE_W;
#pragma unroll
        for (int i = 0; i < 4; i++) {
            int j = i * 256 + tid;
            int r = j >> 3, c = j & 7;
            cp16(&Ab[r * AST + c * 4], g_x + (size_t)(mbase + r) * E_ + k0 + c * 8);
            cp16(&Bb[r * AST + c * 4], g_w + (size_t)(nbase + r) * E_ + k0 + c * 8);
        }
    };

    const int NK = E_ / 64;   // 12
    stage(0, 0);
    CP_COMMIT();

    for (int ks = 0; ks < NK; ks++) {
        CP_WAIT0();
        __syncthreads();
        if (ks + 1 < NK) {
            stage((ks + 1) & 1, (ks + 1) * 64);
            CP_COMMIT();
        }
        const uint32_t Aad = sbase + (ks & 1) * (GEMM_TILE_W * 4)
                           + (wm * 32) * ROWB + aoff;
        const uint32_t Bad = sbase + boffB + (ks & 1) * (GEMM_TILE_W * 4)
                           + (wn * 64) * ROWB + boff;

#pragma unroll
        for (int kk = 0; kk < 4; kk++) {
            uint32_t a[2][4];
#pragma unroll
            for (int mi = 0; mi < 2; mi++)
                ldsm4(a[mi][0], a[mi][1], a[mi][2], a[mi][3],
                      Aad + mi * (16 * ROWB) + kk * 32);
#pragma unroll
            for (int n2 = 0; n2 < 4; n2++) {
                uint32_t b0, b1, b2, b3;
                ldsm4(b0, b1, b2, b3, Bad + n2 * (16 * ROWB) + kk * 32);
#pragma unroll
                for (int mi = 0; mi < 2; mi++) {
                    mma16(acc[mi][2 * n2],     a[mi][0], a[mi][1], a[mi][2], a[mi][3], b0, b1);
                    mma16(acc[mi][2 * n2 + 1], a[mi][0], a[mi][1], a[mi][2], a[mi][3], b2, b3);
                }
            }
        }
    }

#pragma unroll
    for (int mi = 0; mi < 2; mi++) {
#pragma unroll
        for (int ni = 0; ni < 8; ni++) {
            int n = nbase + wn * 64 + ni * 8 + 2 * tg;
            int which = n / E_;
            int n2 = n - which * E_;
            int h = n2 >> 6, d = n2 & 63;
            float b0 = __ldg(bias + n), b1 = __ldg(bias + n + 1);
            __half* basep = (which == 0) ? g_q : ((which == 1) ? g_k : g_v);
#pragma unroll
            for (int half = 0; half < 2; half++) {
                int m = mbase + wm * 32 + mi * 16 + g + half * 8;
                int bb = m >> 11;
                int ss = m & 2047;
                float va = acc[mi][ni][half * 2 + 0] + b0;
                float vb = acc[mi][ni][half * 2 + 1] + b1;
                if (which == 0) { va *= SCALE_; vb *= SCALE_; }
                uint32_t pw = packh2(va, vb);
                size_t rowbase = (((size_t)bb * H_ + h) * S_ + ss);
                reinterpret_cast<uint32_t*>(basep + rowbase * D_)[d >> 1] = pw;
            }
        }
    }
}

// ---------------------------------------------------------------------------
// Kernel 2: causal ReLU attention, fp16 mma + ldmatrix.
// K-super-tile 128, V loaded NATURAL [s][d] and transposed in-register via
// ldmatrix.trans (no vtrans kernel). Balanced 1D work order, register
// S->P->Y dataflow, diagonal fully-masked sub-tile skip.
// ---------------------------------------------------------------------------
#define QBYTES (128 * AST * 4)            // 18432
#define KBUF   (128 * AST * 4)            // 18432 (128 s-rows x 144B)
#define VBUF   (128 * AST * 4)            // 18432 (128 s-rows x 144B)
#define KOFFB  QBYTES
#define VOFFB  (KOFFB + 2 * KBUF)
#define ATTN_SMEM_BYTES (VOFFB + 2 * VBUF)   // 92160

__global__ __launch_bounds__(256, 2) void attn_kernel(float* __restrict__ out)
{
    extern __shared__ uint32_t sh[];
    uint32_t* Qs = sh;                        // [128][36]
    uint32_t* Ks = Qs + 128 * AST;            // [2][128][36]  K [s][d]
    uint32_t* Vs = Ks + 2 * 128 * AST;        // [2][128][36]  V [s][d] natural
    const uint32_t sbase = (uint32_t)__cvta_generic_to_shared(sh);

    const int tid  = threadIdx.x;
    const int lane = tid & 31;
    const int w    = tid >> 5;
    const int g    = lane >> 2;
    const int tg   = lane & 3;

    // balanced mapping: within each bh's 16 ids, interleave heavy/light
    const int id = blockIdx.x;
    const int bh = id >> 4;
    const int j  = id & 15;
    const int qt = (j & 1) ? ((j - 1) >> 1) : (15 - (j >> 1));
    const int qbase = qt * 128;

    const __half* Qg = g_q + ((size_t)bh * S_ + qbase) * D_;
    const __half* Kg = g_k + (size_t)bh * S_ * D_;
    const __half* Vg = g_v + (size_t)bh * S_ * D_;

    const uint32_t aoff  = a_off(lane);   // also the V-trans pattern
    const uint32_t boffK = b_off(lane);

    // stage a 128-s super-tile of K and V (identical addressing)
    auto stageKV = [&](int buf, int kt2) {
        uint32_t* Kb = Ks + buf * (128 * AST);
        uint32_t* Vb = Vs + buf * (128 * AST);
#pragma unroll
        for (int i = 0; i < 4; i++) {
            int jj = i * 256 + tid;
            int r = jj >> 3, c = jj & 7;
            size_t go = (size_t)(kt2 * 128 + r) * D_ + c * 8;
            cp16(&Kb[r * AST + c * 4], Kg + go);
            cp16(&Vb[r * AST + c * 4], Vg + go);
        }
    };

    // prologue: stage Q + first super-tile
#pragma unroll
    for (int i = 0; i < 4; i++) {
        int jj = i * 256 + tid;
        int r = jj >> 3, c = jj & 7;
        cp16(&Qs[r * AST + c * 4], Qg + (size_t)r * D_ + c * 8);
    }
    stageKV(0, 0);
    CP_COMMIT();
    CP_WAIT0();
    __syncthreads();

    // hoist Q fragments (4 k16 groups)
    uint32_t qf[4][4];
    {
        const uint32_t Qad = sbase + (w * 16) * ROWB + aoff;
#pragma unroll
        for (int kk = 0; kk < 4; kk++)
            ldsm4(qf[kk][0], qf[kk][1], qf[kk][2], qf[kk][3], Qad + kk * 32);
    }

    float yacc[8][4];
#pragma unroll
    for (int ni = 0; ni < 8; ni++)
#pragma unroll
        for (int c = 0; c < 4; c++) yacc[ni][c] = 0.f;

    const int r0 = qbase + w * 16 + g;
    const int nkt2 = qt + 1;

    for (int kt2 = 0; kt2 < nkt2; kt2++) {
        if (kt2 > 0) {
            CP_WAIT0();
            __syncthreads();
        }
        if (kt2 + 1 < nkt2) {
            stageKV((kt2 + 1) & 1, kt2 + 1);
            CP_COMMIT();
        }
        const int buf = kt2 & 1;
        const uint32_t Kbase = sbase + KOFFB + buf * KBUF + boffK;
        const uint32_t Vbase = sbase + VOFFB + buf * VBUF + aoff;
        const bool diag = (kt2 == qt);

#pragma unroll
        for (int st = 0; st < 2; st++) {
            // fully-masked sub-tile for this warp? (P == 0 -> no contribution)
            if (diag && (w * 16 + 15) < st * 64) continue;

            const uint32_t Kad = Kbase + st * (64 * ROWB);
            const uint32_t Vad = Vbase + st * (64 * ROWB);

            // ---- S = Q @ K^T : 16 rows x 64 cols ----
            float sacc[8][4];
#pragma unroll
            for (int ni = 0; ni < 8; ni++)
#pragma unroll
                for (int c = 0; c < 4; c++) sacc[ni][c] = 0.f;

#pragma unroll
            for (int kk = 0; kk < 4; kk++) {
#pragma unroll
                for (int n2 = 0; n2 < 4; n2++) {
                    uint32_t b0, b1, b2, b3;
                    ldsm4(b0, b1, b2, b3, Kad + n2 * (16 * ROWB) + kk * 32);
                    mma16(sacc[2 * n2],     qf[kk][0], qf[kk][1], qf[kk][2], qf[kk][3], b0, b1);
                    mma16(sacc[2 * n2 + 1], qf[kk][0], qf[kk][1], qf[kk][2], qf[kk][3], b2, b3);
                }
            }

            // ---- relu (+ mask on diagonal super-tile), pack to A-frags ----
            uint32_t pa[4][4];
            if (diag) {
                const int ktAbs = 2 * kt2 + st;
#pragma unroll
                for (int ni = 0; ni < 8; ni++) {
                    int c0 = ktAbs * 64 + ni * 8 + 2 * tg;
                    float v0 = fmaxf(sacc[ni][0], 0.f);
                    float v1 = fmaxf(sacc[ni][1], 0.f);
                    float v2 = fmaxf(sacc[ni][2], 0.f);
                    float v3 = fmaxf(sacc[ni][3], 0.f);
                    if (c0 > r0)         v0 = 0.f;
                    if (c0 + 1 > r0)     v1 = 0.f;
                    if (c0 > r0 + 8)     v2 = 0.f;
                    if (c0 + 1 > r0 + 8) v3 = 0.f;
                    sacc[ni][0] = v0; sacc[ni][1] = v1;
                    sacc[ni][2] = v2; sacc[ni][3] = v3;
                }
#pragma unroll
                for (int kk = 0; kk < 4; kk++) {
                    pa[kk][0] = packh2(sacc[2 * kk][0],     sacc[2 * kk][1]);
                    pa[kk][1] = packh2(sacc[2 * kk][2],     sacc[2 * kk][3]);
                    pa[kk][2] = packh2(sacc[2 * kk + 1][0], sacc[2 * kk + 1][1]);
                    pa[kk][3] = packh2(sacc[2 * kk + 1][2], sacc[2 * kk + 1][3]);
                }
            } else {
#pragma unroll
                for (int kk = 0; kk < 4; kk++) {
                    pa[kk][0] = hmax2z(packh2(sacc[2 * kk][0],     sacc[2 * kk][1]));
                    pa[kk][1] = hmax2z(packh2(sacc[2 * kk][2],     sacc[2 * kk][3]));
                    pa[kk][2] = hmax2z(packh2(sacc[2 * kk + 1][0], sacc[2 * kk + 1][1]));
                    pa[kk][3] = hmax2z(packh2(sacc[2 * kk + 1][2], sacc[2 * kk + 1][3]));
                }
            }

            // ---- Y += P @ V : V B-frags via ldmatrix.trans on natural [s][d] ----
#pragma unroll
            for (int kk = 0; kk < 4; kk++) {
#pragma unroll
                for (int n2 = 0; n2 < 4; n2++) {
                    uint32_t b0, b1, b2, b3;
                    ldsm4t(b0, b1, b2, b3, Vad + kk * (16 * ROWB) + n2 * 32);
                    mma16(yacc[2 * n2],     pa[kk][0], pa[kk][1], pa[kk][2], pa[kk][3], b0, b1);
                    mma16(yacc[2 * n2 + 1], pa[kk][0], pa[kk][1], pa[kk][2], pa[kk][3], b2, b3);
                }
            }
        }
    }

    // ---- write Y to out [B, S, H, D] ----
    const int b = bh / H_, h = bh % H_;
#pragma unroll
    for (int ni = 0; ni < 8; ni++) {
        int d0 = ni * 8 + 2 * tg;
        float2 v0 = make_float2(yacc[ni][0], yacc[ni][1]);
        *reinterpret_cast<float2*>(
            &out[(((size_t)b * S_ + r0) * H_ + h) * D_ + d0]) = v0;
        float2 v1 = make_float2(yacc[ni][2], yacc[ni][3]);
        *reinterpret_cast<float2*>(
            &out[(((size_t)b * S_ + r0 + 8) * H_ + h) * D_ + d0]) = v1;
    }
}

// ---------------------------------------------------------------------------
extern "C" void kernel_launch(void* const* d_in, const int* in_sizes, int n_in,
                              void* d_out, int out_size)
{
    const float* X    = (const float*)d_in[0];   // [4, 2048, 768]
    const float* W    = (const float*)d_in[1];   // [768, 2304]
    const float* bias = (const float*)d_in[2];   // [2304]
    float* out = (float*)d_out;                  // [4, 2048, 768]

    static bool attr_done = false;
    if (!attr_done) {
        cudaFuncSetAttribute(qkv_gemm,
                             cudaFuncAttributeMaxDynamicSharedMemorySize,
                             GEMM_SMEM_BYTES);
        cudaFuncSetAttribute(attn_kernel,
                             cudaFuncAttributeMaxDynamicSharedMemorySize,
                             ATTN_SMEM_BYTES);
        attr_done = true;
    }

    int n4 = B_ * S_ * E_ / 4;
    cvtx<<<(n4 + 255) / 256, 256>>>((const float4*)X, n4);
    cvtw<<<dim3(3 * E_ / 32, E_ / 32), dim3(32, 8)>>>(W);

    qkv_gemm<<<dim3(3 * E_ / 128, (B_ * S_) / 128), 256, GEMM_SMEM_BYTES>>>(bias);

    attn_kernel<<<(S_ / 128) * B_ * H_, 256, ATTN_SMEM_BYTES>>>(out);
}

// round 11
// speedup vs baseline: 2.2111x; 1.0050x over previous
#include <cuda_runtime.h>
#include <cuda_fp16.h>
#include <cstdint>

// Problem constants
#define B_ 4
#define S_ 2048
#define E_ 768
#define H_ 12
#define D_ 64
#define SCALE_ 0.125f   // 1/sqrt(64)

// Scratch (no cudaMalloc allowed). Natural row-major layouts.
__device__ __align__(16) __half g_x[(size_t)B_ * S_ * E_];         // [m][k]
__device__ __align__(16) __half g_w[(size_t)3 * E_ * E_];          // W^T [n][k]
__device__ __align__(16) __half g_q[(size_t)B_ * H_ * S_ * D_];    // [bh][s][d], pre-scaled 1/8
__device__ __align__(16) __half g_k[(size_t)B_ * H_ * S_ * D_];    // [bh][s][d]
__device__ __align__(16) __half g_v[(size_t)B_ * H_ * S_ * D_];    // [bh][s][d]

// ---------------------------------------------------------------------------
// helpers
// ---------------------------------------------------------------------------
__device__ __forceinline__ uint32_t packh2(float lo, float hi) {
    __half2 h = __floats2half2_rn(lo, hi);
    return *reinterpret_cast<uint32_t*>(&h);
}

__device__ __forceinline__ uint32_t hmax2z(uint32_t x) {
    uint32_t r;
    asm("max.f16x2 %0, %1, %2;" : "=r"(r) : "r"(x), "r"(0u));
    return r;
}

__device__ __forceinline__ void mma16(float c[4],
                                      uint32_t a0, uint32_t a1, uint32_t a2, uint32_t a3,
                                      uint32_t b0, uint32_t b1) {
    asm volatile(
        "mma.sync.aligned.m16n8k16.row.col.f32.f16.f16.f32 "
        "{%0,%1,%2,%3}, {%4,%5,%6,%7}, {%8,%9}, {%0,%1,%2,%3};"
        : "+f"(c[0]), "+f"(c[1]), "+f"(c[2]), "+f"(c[3])
        : "r"(a0), "r"(a1), "r"(a2), "r"(a3), "r"(b0), "r"(b1));
}

__device__ __forceinline__ void ldsm4(uint32_t& r0, uint32_t& r1,
                                      uint32_t& r2, uint32_t& r3, uint32_t addr) {
    asm volatile("ldmatrix.sync.aligned.m8n8.x4.shared.b16 {%0,%1,%2,%3}, [%4];"
                 : "=r"(r0), "=r"(r1), "=r"(r2), "=r"(r3) : "r"(addr));
}

__device__ __forceinline__ void ldsm4t(uint32_t& r0, uint32_t& r1,
                                       uint32_t& r2, uint32_t& r3, uint32_t addr) {
    asm volatile("ldmatrix.sync.aligned.m8n8.x4.trans.shared.b16 {%0,%1,%2,%3}, [%4];"
                 : "=r"(r0), "=r"(r1), "=r"(r2), "=r"(r3) : "r"(addr));
}

__device__ __forceinline__ void cp16(void* sdst, const void* gsrc) {
    uint32_t a = (uint32_t)__cvta_generic_to_shared(sdst);
    asm volatile("cp.async.cg.shared.global [%0], [%1], 16;"
                 :: "r"(a), "l"(gsrc));
}
#define CP_COMMIT() asm volatile("cp.async.commit_group;")
#define CP_WAIT0()  asm volatile("cp.async.wait_group 0;")

// SMEM row stride for 64-half rows: 36 words -> ldmatrix rows hit disjoint
// 4-bank groups (4r mod 32), conflict-free.
#define AST 36
#define ROWB (AST * 4)   // 144 B

// per-lane ldmatrix byte offsets
__device__ __forceinline__ uint32_t a_off(int lane) {
    return (uint32_t)((lane & 15) * ROWB + ((lane & 16) ? 16 : 0));
}
__device__ __forceinline__ uint32_t b_off(int lane) {
    return (uint32_t)(((lane & 7) + ((lane & 16) >> 1)) * ROWB +
                      ((lane & 8) ? 16 : 0));
}

// ---------------------------------------------------------------------------
// Prep: X f32 -> g_x fp16  AND  W [768][2304] f32 -> g_w = W^T fp16, fused.
// ---------------------------------------------------------------------------
#define NXBLK 6144    // (4*2048*768/4) / 256
__global__ void cvt_all(const float4* __restrict__ X4, const float* __restrict__ W)
{
    __shared__ float t[32][33];
    const int tid = threadIdx.x;
    if (blockIdx.x < NXBLK) {
        int i = blockIdx.x * 256 + tid;
        float4 v = X4[i];
        uint2 o = make_uint2(packh2(v.x, v.y), packh2(v.z, v.w));
        *reinterpret_cast<uint2*>(g_x + (size_t)i * 4) = o;
    } else {
        int bw = blockIdx.x - NXBLK;           // 0..1727
        int n0 = (bw % 72) * 32, k0 = (bw / 72) * 32;
        int tx = tid & 31, ty = tid >> 5;
        for (int i = ty; i < 32; i += 8)
            t[i][tx] = W[(size_t)(k0 + i) * (3 * E_) + n0 + tx];
        __syncthreads();
        for (int r = ty; r < 32; r += 8) {
            float v = t[tx][r];
            g_w[(size_t)(n0 + r) * E_ + k0 + tx] = __float2half_rn(v);
        }
    }
}

// ---------------------------------------------------------------------------
// Kernel 1: QKV projection. CTA tile 256x128 (M doubled: W L2 traffic halves),
// 512 threads = 16 warps (8m x 2n), warp 32x64, BK=64, double-buffered cp.async.
// ---------------------------------------------------------------------------
#define GEMM_A_W (256 * AST)
#define GEMM_B_W (128 * AST)
#define GEMM_SMEM_BYTES ((2 * GEMM_A_W + 2 * GEMM_B_W) * 4)   // 110592

__global__ __launch_bounds__(512, 1) void qkv_gemm(const float* __restrict__ bias)
{
    extern __shared__ uint32_t shg[];
    uint32_t* As = shg;                      // [2][256][36]
    uint32_t* Bs = shg + 2 * GEMM_A_W;       // [2][128][36]
    const uint32_t sbase = (uint32_t)__cvta_generic_to_shared(shg);
    const uint32_t boffB = 2 * GEMM_A_W * 4;

    const int tid  = threadIdx.x;
    const int lane = tid & 31;
    const int wid  = tid >> 5;
    const int g    = lane >> 2;
    const int tg   = lane & 3;
    const int wm   = wid & 7;     // 8 warp-rows, 32 rows each
    const int wn   = wid >> 3;    // 2 warp-cols, 64 cols each
    const int mbase = blockIdx.y * 256;
    const int nbase = blockIdx.x * 128;

    const uint32_t aoff = a_off(lane);
    const uint32_t boff = b_off(lane);

    float acc[2][8][4];
#pragma unroll
    for (int mi = 0; mi < 2; mi++)
#pragma unroll
        for (int ni = 0; ni < 8; ni++)
#pragma unroll
            for (int c = 0; c < 4; c++) acc[mi][ni][c] = 0.f;

    auto stage = [&](int buf, int k0) {
        uint32_t* Ab = As + buf * GEMM_A_W;
        uint32_t* Bb = Bs + buf * GEMM_B_W;
#pragma unroll
        for (int i = 0; i < 4; i++) {        // A: 256 rows x 8 chunks = 2048
            int j = i * 512 + tid;
            int r = j >> 3, c = j & 7;
            cp16(&Ab[r * AST + c * 4], g_x + (size_t)(mbase + r) * E_ + k0 + c * 8);
        }
#pragma unroll
        for (int i = 0; i < 2; i++) {        // B: 128 x 8 = 1024
            int j = i * 512 + tid;
            int r = j >> 3, c = j & 7;
            cp16(&Bb[r * AST + c * 4], g_w + (size_t)(nbase + r) * E_ + k0 + c * 8);
        }
    };

    const int NK = E_ / 64;   // 12
    stage(0, 0);
    CP_COMMIT();

    for (int ks = 0; ks < NK; ks++) {
        CP_WAIT0();
        __syncthreads();
        if (ks + 1 < NK) {
            stage((ks + 1) & 1, (ks + 1) * 64);
            CP_COMMIT();
        }
        const uint32_t Aad = sbase + (ks & 1) * (GEMM_A_W * 4)
                           + (wm * 32) * ROWB + aoff;
        const uint32_t Bad = sbase + boffB + (ks & 1) * (GEMM_B_W * 4)
                           + (wn * 64) * ROWB + boff;

#pragma unroll
        for (int kk = 0; kk < 4; kk++) {
            uint32_t a[2][4];
#pragma unroll
            for (int mi = 0; mi < 2; mi++)
                ldsm4(a[mi][0], a[mi][1], a[mi][2], a[mi][3],
                      Aad + mi * (16 * ROWB) + kk * 32);
#pragma unroll
            for (int n2 = 0; n2 < 4; n2++) {
                uint32_t b0, b1, b2, b3;
                ldsm4(b0, b1, b2, b3, Bad + n2 * (16 * ROWB) + kk * 32);
#pragma unroll
                for (int mi = 0; mi < 2; mi++) {
                    mma16(acc[mi][2 * n2],     a[mi][0], a[mi][1], a[mi][2], a[mi][3], b0, b1);
                    mma16(acc[mi][2 * n2 + 1], a[mi][0], a[mi][1], a[mi][2], a[mi][3], b2, b3);
                }
            }
        }
    }

#pragma unroll
    for (int mi = 0; mi < 2; mi++) {
#pragma unroll
        for (int ni = 0; ni < 8; ni++) {
            int n = nbase + wn * 64 + ni * 8 + 2 * tg;
            int which = n / E_;
            int n2 = n - which * E_;
            int h = n2 >> 6, d = n2 & 63;
            float b0 = __ldg(bias + n), b1 = __ldg(bias + n + 1);
            __half* basep = (which == 0) ? g_q : ((which == 1) ? g_k : g_v);
#pragma unroll
            for (int half = 0; half < 2; half++) {
                int m = mbase + wm * 32 + mi * 16 + g + half * 8;
                int bb = m >> 11;
                int ss = m & 2047;
                float va = acc[mi][ni][half * 2 + 0] + b0;
                float vb = acc[mi][ni][half * 2 + 1] + b1;
                if (which == 0) { va *= SCALE_; vb *= SCALE_; }
                uint32_t pw = packh2(va, vb);
                size_t rowbase = (((size_t)bb * H_ + h) * S_ + ss);
                reinterpret_cast<uint32_t*>(basep + rowbase * D_)[d >> 1] = pw;
            }
        }
    }
}

// ---------------------------------------------------------------------------
// Kernel 2: causal ReLU attention, fp16 mma + ldmatrix, K-super-tile 128,
// V transposed in-register (ldmatrix.trans), balanced 1D order, register
// S->P->Y dataflow. NEW: explicit 2-deep ldsm prefetch pipelines in both
// GEMM loops + early V-frag issue under the pack ALU.
// ---------------------------------------------------------------------------
#define QBYTES (128 * AST * 4)
#define KBUF   (128 * AST * 4)
#define VBUF   (128 * AST * 4)
#define KOFFB  QBYTES
#define VOFFB  (KOFFB + 2 * KBUF)
#define ATTN_SMEM_BYTES (VOFFB + 2 * VBUF)   // 92160

__global__ __launch_bounds__(256, 2) void attn_kernel(float* __restrict__ out)
{
    extern __shared__ uint32_t sh[];
    uint32_t* Qs = sh;
    uint32_t* Ks = Qs + 128 * AST;
    uint32_t* Vs = Ks + 2 * 128 * AST;
    const uint32_t sbase = (uint32_t)__cvta_generic_to_shared(sh);

    const int tid  = threadIdx.x;
    const int lane = tid & 31;
    const int w    = tid >> 5;
    const int g    = lane >> 2;
    const int tg   = lane & 3;

    // balanced mapping: within each bh's 16 ids, interleave heavy/light
    const int id = blockIdx.x;
    const int bh = id >> 4;
    const int j  = id & 15;
    const int qt = (j & 1) ? ((j - 1) >> 1) : (15 - (j >> 1));
    const int qbase = qt * 128;

    const __half* Qg = g_q + ((size_t)bh * S_ + qbase) * D_;
    const __half* Kg = g_k + (size_t)bh * S_ * D_;
    const __half* Vg = g_v + (size_t)bh * S_ * D_;

    const uint32_t aoff  = a_off(lane);
    const uint32_t boffK = b_off(lane);

    auto stageKV = [&](int buf, int kt2) {
        uint32_t* Kb = Ks + buf * (128 * AST);
        uint32_t* Vb = Vs + buf * (128 * AST);
#pragma unroll
        for (int i = 0; i < 4; i++) {
            int jj = i * 256 + tid;
            int r = jj >> 3, c = jj & 7;
            size_t go = (size_t)(kt2 * 128 + r) * D_ + c * 8;
            cp16(&Kb[r * AST + c * 4], Kg + go);
            cp16(&Vb[r * AST + c * 4], Vg + go);
        }
    };

#pragma unroll
    for (int i = 0; i < 4; i++) {
        int jj = i * 256 + tid;
        int r = jj >> 3, c = jj & 7;
        cp16(&Qs[r * AST + c * 4], Qg + (size_t)r * D_ + c * 8);
    }
    stageKV(0, 0);
    CP_COMMIT();
    CP_WAIT0();
    __syncthreads();

    // hoist Q fragments (4 k16 groups)
    uint32_t qf[4][4];
    {
        const uint32_t Qad = sbase + (w * 16) * ROWB + aoff;
#pragma unroll
        for (int kk = 0; kk < 4; kk++)
            ldsm4(qf[kk][0], qf[kk][1], qf[kk][2], qf[kk][3], Qad + kk * 32);
    }

    float yacc[8][4];
#pragma unroll
    for (int ni = 0; ni < 8; ni++)
#pragma unroll
        for (int c = 0; c < 4; c++) yacc[ni][c] = 0.f;

    const int r0 = qbase + w * 16 + g;
    const int nkt2 = qt + 1;

    for (int kt2 = 0; kt2 < nkt2; kt2++) {
        if (kt2 > 0) {
            CP_WAIT0();
            __syncthreads();
        }
        if (kt2 + 1 < nkt2) {
            stageKV((kt2 + 1) & 1, kt2 + 1);
            CP_COMMIT();
        }
        const int buf = kt2 & 1;
        const uint32_t Kbase = sbase + KOFFB + buf * KBUF + boffK;
        const uint32_t Vbase = sbase + VOFFB + buf * VBUF + aoff;
        const bool diag = (kt2 == qt);

#pragma unroll
        for (int st = 0; st < 2; st++) {
            if (diag && (w * 16 + 15) < st * 64) continue;   // fully masked

            const uint32_t Kad = Kbase + st * (64 * ROWB);
            const uint32_t Vad = Vbase + st * (64 * ROWB);

            // ---- S = Q @ K^T : 2-deep ldsm prefetch pipeline ----
            float sacc[8][4];
#pragma unroll
            for (int ni = 0; ni < 8; ni++)
#pragma unroll
                for (int c = 0; c < 4; c++) sacc[ni][c] = 0.f;

            uint32_t kb[2][4];
            ldsm4(kb[0][0], kb[0][1], kb[0][2], kb[0][3], Kad);
#pragma unroll
            for (int it = 0; it < 16; it++) {
                const int kk = it >> 2, n2 = it & 3;
                const int cur = it & 1;
                if (it < 15) {
                    const int nx = it + 1;
                    ldsm4(kb[cur ^ 1][0], kb[cur ^ 1][1], kb[cur ^ 1][2], kb[cur ^ 1][3],
                          Kad + (nx & 3) * (16 * ROWB) + (nx >> 2) * 32);
                }
                mma16(sacc[2 * n2],     qf[kk][0], qf[kk][1], qf[kk][2], qf[kk][3],
                      kb[cur][0], kb[cur][1]);
                mma16(sacc[2 * n2 + 1], qf[kk][0], qf[kk][1], qf[kk][2], qf[kk][3],
                      kb[cur][2], kb[cur][3]);
            }

            // early V-frag issue: latency hides under pack ALU below
            uint32_t vb[2][4];
            ldsm4t(vb[0][0], vb[0][1], vb[0][2], vb[0][3], Vad);

            // ---- relu (+ mask on diagonal super-tile), pack to A-frags ----
            uint32_t pa[4][4];
            if (diag) {
                const int ktAbs = 2 * kt2 + st;
#pragma unroll
                for (int ni = 0; ni < 8; ni++) {
                    int c0 = ktAbs * 64 + ni * 8 + 2 * tg;
                    float v0 = fmaxf(sacc[ni][0], 0.f);
                    float v1 = fmaxf(sacc[ni][1], 0.f);
                    float v2 = fmaxf(sacc[ni][2], 0.f);
                    float v3 = fmaxf(sacc[ni][3], 0.f);
                    if (c0 > r0)         v0 = 0.f;
                    if (c0 + 1 > r0)     v1 = 0.f;
                    if (c0 > r0 + 8)     v2 = 0.f;
                    if (c0 + 1 > r0 + 8) v3 = 0.f;
                    sacc[ni][0] = v0; sacc[ni][1] = v1;
                    sacc[ni][2] = v2; sacc[ni][3] = v3;
                }
#pragma unroll
                for (int kk = 0; kk < 4; kk++) {
                    pa[kk][0] = packh2(sacc[2 * kk][0],     sacc[2 * kk][1]);
                    pa[kk][1] = packh2(sacc[2 * kk][2],     sacc[2 * kk][3]);
                    pa[kk][2] = packh2(sacc[2 * kk + 1][0], sacc[2 * kk + 1][1]);
                    pa[kk][3] = packh2(sacc[2 * kk + 1][2], sacc[2 * kk + 1][3]);
                }
            } else {
#pragma unroll
                for (int kk = 0; kk < 4; kk++) {
                    pa[kk][0] = hmax2z(packh2(sacc[2 * kk][0],     sacc[2 * kk][1]));
                    pa[kk][1] = hmax2z(packh2(sacc[2 * kk][2],     sacc[2 * kk][3]));
                    pa[kk][2] = hmax2z(packh2(sacc[2 * kk + 1][0], sacc[2 * kk + 1][1]));
                    pa[kk][3] = hmax2z(packh2(sacc[2 * kk + 1][2], sacc[2 * kk + 1][3]));
                }
            }

            // ---- Y += P @ V : 2-deep ldsm.trans prefetch pipeline ----
#pragma unroll
            for (int it = 0; it < 16; it++) {
                const int kk = it >> 2, n2 = it & 3;
                const int cur = it & 1;
                if (it < 15) {
                    const int nx = it + 1;
                    ldsm4t(vb[cur ^ 1][0], vb[cur ^ 1][1], vb[cur ^ 1][2], vb[cur ^ 1][3],
                           Vad + (nx >> 2) * (16 * ROWB) + (nx & 3) * 32);
                }
                mma16(yacc[2 * n2],     pa[kk][0], pa[kk][1], pa[kk][2], pa[kk][3],
                      vb[cur][0], vb[cur][1]);
                mma16(yacc[2 * n2 + 1], pa[kk][0], pa[kk][1], pa[kk][2], pa[kk][3],
                      vb[cur][2], vb[cur][3]);
            }
        }
    }

    // ---- write Y to out [B, S, H, D] ----
    const int b = bh / H_, h = bh % H_;
#pragma unroll
    for (int ni = 0; ni < 8; ni++) {
        int d0 = ni * 8 + 2 * tg;
        float2 v0 = make_float2(yacc[ni][0], yacc[ni][1]);
        *reinterpret_cast<float2*>(
            &out[(((size_t)b * S_ + r0) * H_ + h) * D_ + d0]) = v0;
        float2 v1 = make_float2(yacc[ni][2], yacc[ni][3]);
        *reinterpret_cast<float2*>(
            &out[(((size_t)b * S_ + r0 + 8) * H_ + h) * D_ + d0]) = v1;
    }
}

// ---------------------------------------------------------------------------
extern "C" void kernel_launch(void* const* d_in, const int* in_sizes, int n_in,
                              void* d_out, int out_size)
{
    const float* X    = (const float*)d_in[0];   // [4, 2048, 768]
    const float* W    = (const float*)d_in[1];   // [768, 2304]
    const float* bias = (const float*)d_in[2];   // [2304]
    float* out = (float*)d_out;                  // [4, 2048, 768]

    static bool attr_done = false;
    if (!attr_done) {
        cudaFuncSetAttribute(qkv_gemm,
                             cudaFuncAttributeMaxDynamicSharedMemorySize,
                             GEMM_SMEM_BYTES);
        cudaFuncSetAttribute(attn_kernel,
                             cudaFuncAttributeMaxDynamicSharedMemorySize,
                             ATTN_SMEM_BYTES);
        attr_done = true;
    }

    // fused prep: 6144 X blocks + 1728 W blocks
    cvt_all<<<NXBLK + (3 * E_ / 32) * (E_ / 32), 256>>>((const float4*)X, W);

    qkv_gemm<<<dim3(3 * E_ / 128, (B_ * S_) / 256), 512, GEMM_SMEM_BYTES>>>(bias);

    attn_kernel<<<(S_ / 128) * B_ * H_, 256, ATTN_SMEM_BYTES>>>(out);
}